// round 2
// baseline (speedup 1.0000x reference)
#include <cuda_runtime.h>
#include <math.h>

#define BB 8
#define CC 512
#define HH 64
#define WW 64
#define HW 4096            // HH*WW

// Scratch (allocation-free: __device__ globals)
__device__ float g_pq[BB * HW * 64];              // [b, pix(h*64+w), o]
__device__ float g_pk[BB * HW * 64];              // [b, pix, o]
__device__ float g_pv[(size_t)BB * HW * CC];      // [b, pix, c]
__device__ float g_att[(size_t)BB * HW * 128];    // [b, h, w, 0:64=attH | 64:128=attW]
__device__ float g_tmpH[(size_t)BB * HW * CC];    // [b, w, h, c]

// ---------------------------------------------------------------------------
// Projection GEMM: out_t[b, pix, o] = bias[o] + sum_c W[o,c] * x[b, c, pix]
// Block tile: 128 pixels x 64 output channels, K-chunks of 64.
// which: 0 -> g_pq, 1 -> g_pk, 2 -> g_pv
// ---------------------------------------------------------------------------
__global__ __launch_bounds__(256) void proj_kernel(
    const float* __restrict__ x, const float* __restrict__ Wm,
    const float* __restrict__ bias, int which, int Ot)
{
    __shared__ float Xs[64][128];   // [c][pix]  32KB
    __shared__ float Ws[64][64];    // [o][c]    16KB
    const int t  = threadIdx.x;
    const int pt = blockIdx.x;      // pixel tile (128 pixels)
    const int ot = blockIdx.y;      // o tile (64 channels)
    const int b  = blockIdx.z;

    float* outp = (which == 0) ? g_pq : (which == 1) ? g_pk : g_pv;

    const float* xb = x + (size_t)b * CC * HW + pt * 128;
    const float* Wb = Wm + (size_t)(ot * 64) * CC;

    float acc[8][4];
#pragma unroll
    for (int i = 0; i < 8; i++)
#pragma unroll
        for (int j = 0; j < 4; j++) acc[i][j] = 0.f;

    const int px4 = t & 31;          // float4 group within 128 pixels
    const int o0  = (t >> 5) * 8;    // uniform per warp -> smem broadcast

    for (int c0 = 0; c0 < CC; c0 += 64) {
#pragma unroll
        for (int i = 0; i < 8; i++) {                 // 2048 float4 total
            int idx = t + i * 256;
            int c = idx >> 5, p4 = idx & 31;
            ((float4*)&Xs[c][0])[p4] =
                ((const float4*)(xb + (size_t)(c0 + c) * HW))[p4];
        }
#pragma unroll
        for (int i = 0; i < 16; i++) {                // 4096 floats
            int idx = t + i * 256;
            int o = idx >> 6, c = idx & 63;
            Ws[o][c] = Wb[(size_t)o * CC + c0 + c];
        }
        __syncthreads();
#pragma unroll 8
        for (int c = 0; c < 64; c++) {
            float4 xv = ((float4*)&Xs[c][0])[px4];
#pragma unroll
            for (int oi = 0; oi < 8; oi++) {
                float w = Ws[o0 + oi][c];
                acc[oi][0] += w * xv.x;
                acc[oi][1] += w * xv.y;
                acc[oi][2] += w * xv.z;
                acc[oi][3] += w * xv.w;
            }
        }
        __syncthreads();
    }

    float bv[8];
#pragma unroll
    for (int oi = 0; oi < 8; oi++) bv[oi] = bias[ot * 64 + o0 + oi];

    const int pixbase = pt * 128 + px4 * 4;
#pragma unroll
    for (int pi = 0; pi < 4; pi++) {
        size_t oidx = ((size_t)b * HW + pixbase + pi) * Ot + ot * 64 + o0;
        float4 v1, v2;
        v1.x = acc[0][pi] + bv[0]; v1.y = acc[1][pi] + bv[1];
        v1.z = acc[2][pi] + bv[2]; v1.w = acc[3][pi] + bv[3];
        v2.x = acc[4][pi] + bv[4]; v2.y = acc[5][pi] + bv[5];
        v2.z = acc[6][pi] + bv[6]; v2.w = acc[7][pi] + bv[7];
        *(float4*)(outp + oidx)     = v1;
        *(float4*)(outp + oidx + 4) = v2;
    }
}

// ---------------------------------------------------------------------------
// Attention scores.
// mode 0: per (b, w):  S[h][g] = pq[.,h,w] . pk[.,g,w], diag masked -> att[...,g]
// mode 1: per (b, h):  S[w][f] = pq[.,h,w] . pk[.,h,f]           -> att[...,64+f]
// ---------------------------------------------------------------------------
__global__ __launch_bounds__(256) void scores_kernel(int mode)
{
    __shared__ float As[64][65];
    __shared__ float Bs[64][65];
    const int t = threadIdx.x;
    const int q = blockIdx.x;   // w (mode 0) or h (mode 1)
    const int b = blockIdx.y;

    size_t base; int rs;
    if (mode == 0) { base = ((size_t)b * HW + q) * 64;      rs = 4096; }
    else           { base = ((size_t)b * HW + q * 64) * 64; rs = 64;   }

    for (int idx = t; idx < 4096; idx += 256) {
        int i = idx >> 6, c = idx & 63;
        As[i][c] = g_pq[base + (size_t)i * rs + c];
        Bs[i][c] = g_pk[base + (size_t)i * rs + c];
    }
    __syncthreads();

    const int i0 = (t & 15) * 4;
    const int j0 = (t >> 4) * 4;
    float acc[4][4];
#pragma unroll
    for (int ii = 0; ii < 4; ii++)
#pragma unroll
        for (int jj = 0; jj < 4; jj++) acc[ii][jj] = 0.f;

#pragma unroll 8
    for (int c = 0; c < 64; c++) {
        float a[4], bb[4];
#pragma unroll
        for (int k = 0; k < 4; k++) { a[k] = As[i0 + k][c]; bb[k] = Bs[j0 + k][c]; }
#pragma unroll
        for (int ii = 0; ii < 4; ii++)
#pragma unroll
            for (int jj = 0; jj < 4; jj++) acc[ii][jj] += a[ii] * bb[jj];
    }

#pragma unroll
    for (int ii = 0; ii < 4; ii++) {
#pragma unroll
        for (int jj = 0; jj < 4; jj++) {
            int i = i0 + ii, j = j0 + jj;
            float v = acc[ii][jj];
            size_t o;
            if (mode == 0) {
                if (i == j) v = -1e30f;  // diagonal mask (exp -> 0)
                o = (((size_t)b * HH + i) * WW + q) * 128 + j;
            } else {
                o = (((size_t)b * HH + q) * WW + i) * 128 + 64 + j;
            }
            g_att[o] = v;
        }
    }
}

// ---------------------------------------------------------------------------
// Softmax over the 128 concatenated logits. One warp per row.
// ---------------------------------------------------------------------------
__global__ __launch_bounds__(256) void softmax_kernel()
{
    const int r    = (blockIdx.x * 256 + threadIdx.x) >> 5;   // 32768 rows
    const int lane = threadIdx.x & 31;
    float4* row = (float4*)(g_att + (size_t)r * 128);
    float4 v = row[lane];
    float m = fmaxf(fmaxf(v.x, v.y), fmaxf(v.z, v.w));
#pragma unroll
    for (int o = 16; o > 0; o >>= 1) m = fmaxf(m, __shfl_xor_sync(0xffffffffu, m, o));
    v.x = __expf(v.x - m); v.y = __expf(v.y - m);
    v.z = __expf(v.z - m); v.w = __expf(v.w - m);
    float s = v.x + v.y + v.z + v.w;
#pragma unroll
    for (int o = 16; o > 0; o >>= 1) s += __shfl_xor_sync(0xffffffffu, s, o);
    float inv = 1.0f / s;
    v.x *= inv; v.y *= inv; v.z *= inv; v.w *= inv;
    row[lane] = v;
}

// ---------------------------------------------------------------------------
// tmpH[b, w, h, c] = sum_g attH[b,h,w,g] * pv[b, pix(g,w), c]   (per (b,w) block)
// ---------------------------------------------------------------------------
__global__ __launch_bounds__(256) void tmph_kernel()
{
    __shared__ float Att[64][65];   // [h][g]
    __shared__ float Ps[64][64];    // [g][c-chunk]
    const int t = threadIdx.x, w = blockIdx.x, b = blockIdx.y;

    for (int idx = t; idx < 4096; idx += 256) {
        int h = idx >> 6, g = idx & 63;
        Att[h][g] = g_att[(((size_t)b * HH + h) * WW + w) * 128 + g];
    }

    const int c4 = t & 15;
    const int h0 = (t >> 4) * 4;

    for (int c0 = 0; c0 < CC; c0 += 64) {
        __syncthreads();
        for (int idx = t; idx < 4096; idx += 256) {
            int g = idx >> 6, c = idx & 63;
            Ps[g][c] = g_pv[((size_t)b * HW + g * WW + w) * CC + c0 + c];
        }
        __syncthreads();

        float4 a0 = {0,0,0,0}, a1 = {0,0,0,0}, a2 = {0,0,0,0}, a3 = {0,0,0,0};
#pragma unroll 8
        for (int g = 0; g < 64; g++) {
            float4 p = ((float4*)&Ps[g][0])[c4];
            float t0 = Att[h0 + 0][g], t1 = Att[h0 + 1][g];
            float t2 = Att[h0 + 2][g], t3 = Att[h0 + 3][g];
            a0.x += t0 * p.x; a0.y += t0 * p.y; a0.z += t0 * p.z; a0.w += t0 * p.w;
            a1.x += t1 * p.x; a1.y += t1 * p.y; a1.z += t1 * p.z; a1.w += t1 * p.w;
            a2.x += t2 * p.x; a2.y += t2 * p.y; a2.z += t2 * p.z; a2.w += t2 * p.w;
            a3.x += t3 * p.x; a3.y += t3 * p.y; a3.z += t3 * p.z; a3.w += t3 * p.w;
        }
        float* dst = g_tmpH + (((size_t)b * WW + w) * HH) * CC + c0;
        ((float4*)(dst + (size_t)(h0 + 0) * CC))[c4] = a0;
        ((float4*)(dst + (size_t)(h0 + 1) * CC))[c4] = a1;
        ((float4*)(dst + (size_t)(h0 + 2) * CC))[c4] = a2;
        ((float4*)(dst + (size_t)(h0 + 3) * CC))[c4] = a3;
    }
}

// ---------------------------------------------------------------------------
// Final (per (b,h) block):
// out[b,c,h,w] = value[b,c,h,w]
//              + gamma * ( tmpH[b,w,h,c] + sum_f attW[b,h,w,f] * pv[b,pix(h,f),c] )
// ---------------------------------------------------------------------------
__global__ __launch_bounds__(256) void final_kernel(
    const float* __restrict__ value, const float* __restrict__ gamma,
    float* __restrict__ out)
{
    __shared__ float Att[64][65];   // [w][f]
    __shared__ float Ps[64][64];    // [f][c-chunk]
    const int t = threadIdx.x, h = blockIdx.x, b = blockIdx.y;
    const float gm = gamma[0];

    for (int idx = t; idx < 4096; idx += 256) {
        int w = idx >> 6, f = idx & 63;
        Att[w][f] = g_att[(((size_t)b * HH + h) * WW + w) * 128 + 64 + f];
    }

    const int w4 = t & 15;          // owns w = w4*4 .. w4*4+3 (contiguous)
    const int cg = t >> 4;          // c-chunk group: c = c0 + cg*4 .. +3

    for (int c0 = 0; c0 < CC; c0 += 64) {
        __syncthreads();
        for (int idx = t; idx < 4096; idx += 256) {
            int f = idx >> 6, c = idx & 63;
            Ps[f][c] = g_pv[((size_t)b * HW + h * WW + f) * CC + c0 + c];
        }
        __syncthreads();

        float acc[4][4];  // [ci][wi]
#pragma unroll
        for (int ci = 0; ci < 4; ci++)
#pragma unroll
            for (int wi = 0; wi < 4; wi++) acc[ci][wi] = 0.f;

#pragma unroll 8
        for (int f = 0; f < 64; f++) {
            float p0 = Ps[f][cg * 4 + 0], p1 = Ps[f][cg * 4 + 1];
            float p2 = Ps[f][cg * 4 + 2], p3 = Ps[f][cg * 4 + 3];
            float w0 = Att[w4 * 4 + 0][f], w1 = Att[w4 * 4 + 1][f];
            float w2 = Att[w4 * 4 + 2][f], w3 = Att[w4 * 4 + 3][f];
            acc[0][0] += p0 * w0; acc[0][1] += p0 * w1; acc[0][2] += p0 * w2; acc[0][3] += p0 * w3;
            acc[1][0] += p1 * w0; acc[1][1] += p1 * w1; acc[1][2] += p1 * w2; acc[1][3] += p1 * w3;
            acc[2][0] += p2 * w0; acc[2][1] += p2 * w1; acc[2][2] += p2 * w2; acc[2][3] += p2 * w3;
            acc[3][0] += p3 * w0; acc[3][1] += p3 * w1; acc[3][2] += p3 * w2; acc[3][3] += p3 * w3;
        }

        // tmpH for this thread's 4 w-rows, float4 along c (coalesced 32B granules)
        float th[4][4];
#pragma unroll
        for (int wi = 0; wi < 4; wi++) {
            float4 v4 = ((const float4*)(g_tmpH +
                (((size_t)b * WW + w4 * 4 + wi) * HH + h) * CC + c0))[cg];
            th[wi][0] = v4.x; th[wi][1] = v4.y; th[wi][2] = v4.z; th[wi][3] = v4.w;
        }

#pragma unroll
        for (int ci = 0; ci < 4; ci++) {
            int c = c0 + cg * 4 + ci;
            size_t vbase = (((size_t)b * CC + c) * HH + h) * WW;
            float4 vv = ((const float4*)(value + vbase))[w4];
            float4 ov;
            ov.x = vv.x + gm * (acc[ci][0] + th[0][ci]);
            ov.y = vv.y + gm * (acc[ci][1] + th[1][ci]);
            ov.z = vv.z + gm * (acc[ci][2] + th[2][ci]);
            ov.w = vv.w + gm * (acc[ci][3] + th[3][ci]);
            ((float4*)(out + vbase))[w4] = ov;
        }
    }
}

// ---------------------------------------------------------------------------
extern "C" void kernel_launch(void* const* d_in, const int* in_sizes, int n_in,
                              void* d_out, int out_size)
{
    (void)in_sizes; (void)n_in; (void)out_size;
    const float* query = (const float*)d_in[0];
    const float* key_t = (const float*)d_in[1];
    const float* value = (const float*)d_in[2];
    const float* Wq    = (const float*)d_in[3];
    const float* bq    = (const float*)d_in[4];
    const float* Wk    = (const float*)d_in[5];
    const float* bk    = (const float*)d_in[6];
    const float* Wv    = (const float*)d_in[7];
    const float* bv    = (const float*)d_in[8];
    const float* gamma = (const float*)d_in[9];
    float* out = (float*)d_out;

    proj_kernel<<<dim3(32, 1, BB), 256>>>(query, Wq, bq, 0, 64);
    proj_kernel<<<dim3(32, 1, BB), 256>>>(key_t, Wk, bk, 1, 64);
    proj_kernel<<<dim3(32, 8, BB), 256>>>(value, Wv, bv, 2, CC);

    scores_kernel<<<dim3(WW, BB), 256>>>(0);   // eH (+ diag mask)
    scores_kernel<<<dim3(HH, BB), 256>>>(1);   // eW

    softmax_kernel<<<4096, 256>>>();

    tmph_kernel<<<dim3(WW, BB), 256>>>();
    final_kernel<<<dim3(HH, BB), 256>>>(value, gamma, out);
}

// round 6
// speedup vs baseline: 1.2630x; 1.2630x over previous
#include <cuda_runtime.h>
#include <mma.h>
#include <math.h>

using namespace nvcuda;

#define BB 8
#define CC 512
#define HH 64
#define WW 64
#define HW 4096            // HH*WW

// Scratch (allocation-free: __device__ globals)
__device__ float g_pq[BB * HW * 64];              // [b, pix(h*64+w), o]   (tf32-rounded)
__device__ float g_pk[BB * HW * 64];              // [b, pix, o]           (tf32-rounded)
__device__ float g_pv[(size_t)BB * HW * CC];      // [b, pix, c]
__device__ float g_att[(size_t)BB * HW * 128];    // [b, h, w, 0:64=attH | 64:128=attW]
__device__ float g_tmpH[(size_t)BB * HW * CC];    // [b, w, h, c]

// ---------------------------------------------------------------------------
// Projection GEMM via tf32 WMMA:
//   out[b, pix, o] = bias[o] + sum_c W[o,c] * x[b, c, pix]
// Block tile: 64 pixels x 64 o-channels, K chunks of 64.
// 8 warps: warp = (wp in 0..3 -> 16 pix) x (wo in 0..1 -> 32 o = 2 frags)
// which: 0 -> g_pq, 1 -> g_pk, 2 -> g_pv
// ---------------------------------------------------------------------------
__global__ __launch_bounds__(256) void proj_wmma(
    const float* __restrict__ x, const float* __restrict__ Wm,
    const float* __restrict__ bias, int which, int Ot)
{
    __shared__ float Xs[64][68];   // [c][pix], tf32 values; reused as out [pix][o]
    __shared__ float Ws[64][68];   // [o][c],   tf32 values

    const int t  = threadIdx.x;
    const int pt = blockIdx.x;     // 64-pixel tile
    const int ot = blockIdx.y;     // 64-o tile
    const int b  = blockIdx.z;
    const int warp = t >> 5;
    const int wp = warp >> 1;      // pixel sub-tile (16)
    const int wo = warp & 1;       // o half (32 = 2 frags)

    float* outp = (which == 0) ? g_pq : (which == 1) ? g_pk : g_pv;
    const float* xb = x + (size_t)b * CC * HW + pt * 64;
    const float* Wb = Wm + (size_t)(ot * 64) * CC;

    wmma::fragment<wmma::accumulator, 16, 16, 8, float> acc[2];
    wmma::fill_fragment(acc[0], 0.0f);
    wmma::fill_fragment(acc[1], 0.0f);

    for (int c0 = 0; c0 < CC; c0 += 64) {
#pragma unroll
        for (int i = 0; i < 4; i++) {              // Xs: 1024 float4
            int idx = t + i * 256;
            int c = idx >> 4, p4 = idx & 15;
            float4 v = ((const float4*)(xb + (size_t)(c0 + c) * HW))[p4];
            v.x = wmma::__float_to_tf32(v.x); v.y = wmma::__float_to_tf32(v.y);
            v.z = wmma::__float_to_tf32(v.z); v.w = wmma::__float_to_tf32(v.w);
            ((float4*)&Xs[c][0])[p4] = v;
        }
#pragma unroll
        for (int i = 0; i < 4; i++) {              // Ws: 1024 float4
            int idx = t + i * 256;
            int o = idx >> 4, c4 = idx & 15;
            float4 v = ((const float4*)(Wb + (size_t)o * CC + c0))[c4];
            v.x = wmma::__float_to_tf32(v.x); v.y = wmma::__float_to_tf32(v.y);
            v.z = wmma::__float_to_tf32(v.z); v.w = wmma::__float_to_tf32(v.w);
            ((float4*)&Ws[o][0])[c4] = v;
        }
        __syncthreads();

#pragma unroll
        for (int k = 0; k < 8; k++) {
            wmma::fragment<wmma::matrix_a, 16, 16, 8, wmma::precision::tf32,
                           wmma::col_major> a;
            wmma::load_matrix_sync(a, &Xs[k * 8][wp * 16], 68);
#pragma unroll
            for (int oi = 0; oi < 2; oi++) {
                wmma::fragment<wmma::matrix_b, 16, 16, 8, wmma::precision::tf32,
                               wmma::col_major> bf;
                wmma::load_matrix_sync(bf, &Ws[wo * 32 + oi * 16][k * 8], 68);
                wmma::mma_sync(acc[oi], a, bf, acc[oi]);
            }
        }
        __syncthreads();
    }

    // Stage result [pix][o] into Xs, then write with bias (coalesced along o)
#pragma unroll
    for (int oi = 0; oi < 2; oi++)
        wmma::store_matrix_sync(&Xs[wp * 16][wo * 32 + oi * 16], acc[oi], 68,
                                wmma::mem_row_major);
    __syncthreads();

#pragma unroll
    for (int i = 0; i < 4; i++) {
        int idx = t + i * 256;
        int pix = idx >> 4, og = idx & 15;
        float4 v  = ((float4*)&Xs[pix][0])[og];
        float4 bi = ((const float4*)(bias + ot * 64))[og];
        v.x += bi.x; v.y += bi.y; v.z += bi.z; v.w += bi.w;
        *(float4*)(outp + ((size_t)b * HW + pt * 64 + pix) * Ot + ot * 64 + og * 4) = v;
    }
}

// ---------------------------------------------------------------------------
// Attention scores (kept in fp32 to limit softmax-logit error).
// mode 0: per (b, w):  S[h][g] = pq[.,h,w] . pk[.,g,w], diag masked -> att[...,g]
// mode 1: per (b, h):  S[w][f] = pq[.,h,w] . pk[.,h,f]           -> att[...,64+f]
// ---------------------------------------------------------------------------
__global__ __launch_bounds__(256) void scores_kernel(int mode)
{
    __shared__ float As[64][65];
    __shared__ float Bs[64][65];
    const int t = threadIdx.x;
    const int q = blockIdx.x;
    const int b = blockIdx.y;

    size_t base; int rs;
    if (mode == 0) { base = ((size_t)b * HW + q) * 64;      rs = 4096; }
    else           { base = ((size_t)b * HW + q * 64) * 64; rs = 64;   }

    for (int idx = t; idx < 4096; idx += 256) {
        int i = idx >> 6, c = idx & 63;
        As[i][c] = g_pq[base + (size_t)i * rs + c];
        Bs[i][c] = g_pk[base + (size_t)i * rs + c];
    }
    __syncthreads();

    const int i0 = (t & 15) * 4;
    const int j0 = (t >> 4) * 4;
    float acc[4][4];
#pragma unroll
    for (int ii = 0; ii < 4; ii++)
#pragma unroll
        for (int jj = 0; jj < 4; jj++) acc[ii][jj] = 0.f;

#pragma unroll 8
    for (int c = 0; c < 64; c++) {
        float a[4], bb[4];
#pragma unroll
        for (int k = 0; k < 4; k++) { a[k] = As[i0 + k][c]; bb[k] = Bs[j0 + k][c]; }
#pragma unroll
        for (int ii = 0; ii < 4; ii++)
#pragma unroll
            for (int jj = 0; jj < 4; jj++) acc[ii][jj] += a[ii] * bb[jj];
    }

#pragma unroll
    for (int ii = 0; ii < 4; ii++) {
#pragma unroll
        for (int jj = 0; jj < 4; jj++) {
            int i = i0 + ii, j = j0 + jj;
            float v = acc[ii][jj];
            size_t o;
            if (mode == 0) {
                if (i == j) v = -1e30f;
                o = (((size_t)b * HH + i) * WW + q) * 128 + j;
            } else {
                o = (((size_t)b * HH + q) * WW + i) * 128 + 64 + j;
            }
            g_att[o] = v;
        }
    }
}

// ---------------------------------------------------------------------------
// Softmax over the 128 concatenated logits. One warp per row.
// ---------------------------------------------------------------------------
__global__ __launch_bounds__(256) void softmax_kernel()
{
    const int r    = (blockIdx.x * 256 + threadIdx.x) >> 5;
    const int lane = threadIdx.x & 31;
    float4* row = (float4*)(g_att + (size_t)r * 128);
    float4 v = row[lane];
    float m = fmaxf(fmaxf(v.x, v.y), fmaxf(v.z, v.w));
#pragma unroll
    for (int o = 16; o > 0; o >>= 1) m = fmaxf(m, __shfl_xor_sync(0xffffffffu, m, o));
    v.x = __expf(v.x - m); v.y = __expf(v.y - m);
    v.z = __expf(v.z - m); v.w = __expf(v.w - m);
    float s = v.x + v.y + v.z + v.w;
#pragma unroll
    for (int o = 16; o > 0; o >>= 1) s += __shfl_xor_sync(0xffffffffu, s, o);
    float inv = 1.0f / s;
    v.x *= inv; v.y *= inv; v.z *= inv; v.w *= inv;
    row[lane] = v;
}

// ---------------------------------------------------------------------------
// tmpH[b, w, h, c] = sum_g attH[b,h,w,g] * pv[b, pix(g,w), c]  via tf32 WMMA.
// Per (b,w): M=64 (h) x N=512 (c, chunks of 64) x K=64 (g).
// ---------------------------------------------------------------------------
__global__ __launch_bounds__(256) void tmph_wmma()
{
    __shared__ float Att[64][68];   // [h][g] tf32
    __shared__ float Ps[64][68];    // [g][c] tf32
    const int t = threadIdx.x, w = blockIdx.x, b = blockIdx.y;
    const int warp = t >> 5;
    const int wh = warp >> 1;       // h sub-tile (16)
    const int wc = warp & 1;        // c half (32 = 2 frags)

#pragma unroll
    for (int i = 0; i < 4; i++) {   // Att: 1024 float4
        int idx = t + i * 256;
        int h = idx >> 4, g4 = idx & 15;
        float4 v = *(const float4*)(g_att + (((size_t)b * HH + h) * WW + w) * 128 + g4 * 4);
        v.x = wmma::__float_to_tf32(v.x); v.y = wmma::__float_to_tf32(v.y);
        v.z = wmma::__float_to_tf32(v.z); v.w = wmma::__float_to_tf32(v.w);
        ((float4*)&Att[h][0])[g4] = v;
    }

    for (int c0 = 0; c0 < CC; c0 += 64) {
        __syncthreads();            // covers Att staging + prior chunk's mma reads
#pragma unroll
        for (int i = 0; i < 4; i++) {
            int idx = t + i * 256;
            int g = idx >> 4, c4 = idx & 15;
            float4 v = *(const float4*)(g_pv + ((size_t)b * HW + g * WW + w) * CC + c0 + c4 * 4);
            v.x = wmma::__float_to_tf32(v.x); v.y = wmma::__float_to_tf32(v.y);
            v.z = wmma::__float_to_tf32(v.z); v.w = wmma::__float_to_tf32(v.w);
            ((float4*)&Ps[g][0])[c4] = v;
        }
        __syncthreads();

        wmma::fragment<wmma::accumulator, 16, 16, 8, float> acc[2];
        wmma::fill_fragment(acc[0], 0.0f);
        wmma::fill_fragment(acc[1], 0.0f);
#pragma unroll
        for (int k = 0; k < 8; k++) {
            wmma::fragment<wmma::matrix_a, 16, 16, 8, wmma::precision::tf32,
                           wmma::row_major> a;
            wmma::load_matrix_sync(a, &Att[wh * 16][k * 8], 68);
#pragma unroll
            for (int ci = 0; ci < 2; ci++) {
                wmma::fragment<wmma::matrix_b, 16, 16, 8, wmma::precision::tf32,
                               wmma::row_major> bf;
                wmma::load_matrix_sync(bf, &Ps[k * 8][wc * 32 + ci * 16], 68);
                wmma::mma_sync(acc[ci], a, bf, acc[ci]);
            }
        }
        // store straight to gmem (disjoint tiles; no smem hazard)
        float* dst = g_tmpH + (((size_t)b * WW + w) * HH + wh * 16) * CC + c0;
#pragma unroll
        for (int ci = 0; ci < 2; ci++)
            wmma::store_matrix_sync(dst + wc * 32 + ci * 16, acc[ci], CC,
                                    wmma::mem_row_major);
    }
}

// ---------------------------------------------------------------------------
// Final (per (b,h)): Sw[w][c] = sum_f attW[b,h,w,f] * pv[b, pix(h,f), c] via WMMA;
// out[b,c,h,w] = value + gamma * (Sw[w][c] + tmpH[b,w,h,c])
// ---------------------------------------------------------------------------
__global__ __launch_bounds__(256) void final_wmma(
    const float* __restrict__ value, const float* __restrict__ gamma,
    float* __restrict__ out)
{
    __shared__ float Att[64][68];   // [w][f] tf32
    __shared__ float PsO[64][68];   // Ps [f][c] tf32, then reused as Osm [w][c]
    const int t = threadIdx.x, h = blockIdx.x, b = blockIdx.y;
    const int warp = t >> 5;
    const int wh = warp >> 1;       // w sub-tile (16)
    const int wc = warp & 1;        // c half (32 = 2 frags)
    const float gm = gamma[0];

#pragma unroll
    for (int i = 0; i < 4; i++) {
        int idx = t + i * 256;
        int w = idx >> 4, f4 = idx & 15;
        float4 v = *(const float4*)(g_att + (((size_t)b * HH + h) * WW + w) * 128 + 64 + f4 * 4);
        v.x = wmma::__float_to_tf32(v.x); v.y = wmma::__float_to_tf32(v.y);
        v.z = wmma::__float_to_tf32(v.z); v.w = wmma::__float_to_tf32(v.w);
        ((float4*)&Att[w][0])[f4] = v;
    }

    const int w4 = t & 15;          // epilogue: 4 consecutive w
    const int cg = t >> 4;          // epilogue: 4 consecutive c

    for (int c0 = 0; c0 < CC; c0 += 64) {
        __syncthreads();            // prior epilogue reads of PsO done; Att staged
#pragma unroll
        for (int i = 0; i < 4; i++) {
            int idx = t + i * 256;
            int f = idx >> 4, c4 = idx & 15;
            float4 v = *(const float4*)(g_pv + ((size_t)b * HW + h * WW + f) * CC + c0 + c4 * 4);
            v.x = wmma::__float_to_tf32(v.x); v.y = wmma::__float_to_tf32(v.y);
            v.z = wmma::__float_to_tf32(v.z); v.w = wmma::__float_to_tf32(v.w);
            ((float4*)&PsO[f][0])[c4] = v;
        }
        __syncthreads();

        wmma::fragment<wmma::accumulator, 16, 16, 8, float> acc[2];
        wmma::fill_fragment(acc[0], 0.0f);
        wmma::fill_fragment(acc[1], 0.0f);
#pragma unroll
        for (int k = 0; k < 8; k++) {
            wmma::fragment<wmma::matrix_a, 16, 16, 8, wmma::precision::tf32,
                           wmma::row_major> a;
            wmma::load_matrix_sync(a, &Att[wh * 16][k * 8], 68);
#pragma unroll
            for (int ci = 0; ci < 2; ci++) {
                wmma::fragment<wmma::matrix_b, 16, 16, 8, wmma::precision::tf32,
                               wmma::row_major> bf;
                wmma::load_matrix_sync(bf, &PsO[k * 8][wc * 32 + ci * 16], 68);
                wmma::mma_sync(acc[ci], a, bf, acc[ci]);
            }
        }
        __syncthreads();            // all warps done reading PsO before overwrite

#pragma unroll
        for (int ci = 0; ci < 2; ci++)
            wmma::store_matrix_sync(&PsO[wh * 16][wc * 32 + ci * 16], acc[ci], 68,
                                    wmma::mem_row_major);   // Osm[w][c]
        __syncthreads();

        // Epilogue: combine Osm + tmpH + value -> out  (float4 along w)
        float th[4][4];   // [wi][ci]
#pragma unroll
        for (int wi = 0; wi < 4; wi++) {
            float4 v4 = *(const float4*)(g_tmpH +
                (((size_t)b * WW + w4 * 4 + wi) * HH + h) * CC + c0 + cg * 4);
            th[wi][0] = v4.x; th[wi][1] = v4.y; th[wi][2] = v4.z; th[wi][3] = v4.w;
        }
#pragma unroll
        for (int ci = 0; ci < 4; ci++) {
            int c = c0 + cg * 4 + ci;
            size_t vbase = (((size_t)b * CC + c) * HH + h) * WW;
            float4 vv = ((const float4*)(value + vbase))[w4];
            float4 ov;
            ov.x = vv.x + gm * (PsO[w4 * 4 + 0][cg * 4 + ci] + th[0][ci]);
            ov.y = vv.y + gm * (PsO[w4 * 4 + 1][cg * 4 + ci] + th[1][ci]);
            ov.z = vv.z + gm * (PsO[w4 * 4 + 2][cg * 4 + ci] + th[2][ci]);
            ov.w = vv.w + gm * (PsO[w4 * 4 + 3][cg * 4 + ci] + th[3][ci]);
            ((float4*)(out + vbase))[w4] = ov;
        }
    }
}

// ---------------------------------------------------------------------------
extern "C" void kernel_launch(void* const* d_in, const int* in_sizes, int n_in,
                              void* d_out, int out_size)
{
    (void)in_sizes; (void)n_in; (void)out_size;
    const float* query = (const float*)d_in[0];
    const float* key_t = (const float*)d_in[1];
    const float* value = (const float*)d_in[2];
    const float* Wq    = (const float*)d_in[3];
    const float* bq    = (const float*)d_in[4];
    const float* Wk    = (const float*)d_in[5];
    const float* bk    = (const float*)d_in[6];
    const float* Wv    = (const float*)d_in[7];
    const float* bv    = (const float*)d_in[8];
    const float* gamma = (const float*)d_in[9];
    float* out = (float*)d_out;

    proj_wmma<<<dim3(64, 1, BB), 256>>>(query, Wq, bq, 0, 64);
    proj_wmma<<<dim3(64, 1, BB), 256>>>(key_t, Wk, bk, 1, 64);
    proj_wmma<<<dim3(64, 8, BB), 256>>>(value, Wv, bv, 2, CC);

    scores_kernel<<<dim3(WW, BB), 256>>>(0);   // eH (+ diag mask)
    scores_kernel<<<dim3(HH, BB), 256>>>(1);   // eW

    softmax_kernel<<<4096, 256>>>();

    tmph_wmma<<<dim3(WW, BB), 256>>>();
    final_wmma<<<dim3(HH, BB), 256>>>(value, gamma, out);
}

// round 7
// speedup vs baseline: 1.4071x; 1.1141x over previous
#include <cuda_runtime.h>
#include <mma.h>
#include <math.h>

using namespace nvcuda;

#define BB 8
#define CC 512
#define HH 64
#define WW 64
#define HW 4096            // HH*WW

// Scratch (allocation-free: __device__ globals). Projections stored WITHOUT bias.
__device__ float g_pq[BB * HW * 64];              // [b, pix(h*64+w), o]
__device__ float g_pk[BB * HW * 64];              // [b, pix, o]
__device__ float g_pv[(size_t)BB * HW * CC];      // [b, pix, c]
__device__ float g_att[(size_t)BB * HW * 128];    // [b, h, w, 0:64=attH | 64:128=attW]
__device__ float g_tmpH[(size_t)BB * HW * CC];    // [b, w, h, c]

__device__ __forceinline__ float4 tf32x4(float4 v) {
    v.x = wmma::__float_to_tf32(v.x); v.y = wmma::__float_to_tf32(v.y);
    v.z = wmma::__float_to_tf32(v.z); v.w = wmma::__float_to_tf32(v.w);
    return v;
}

// ---------------------------------------------------------------------------
// q/k projection (no bias): out[b,pix,o] = sum_c W[o,c] * x[b,c,pix]
// Block: 128 pixels x 64 o.  8 warps = 4(m:32) x 2(n:32), acc 2x2 frags.
// blockIdx.y: 0 -> (query,Wq,g_pq), 1 -> (key_t,Wk,g_pk)
// ---------------------------------------------------------------------------
__global__ __launch_bounds__(256) void proj_qk(
    const float* __restrict__ q, const float* __restrict__ Wq,
    const float* __restrict__ kk, const float* __restrict__ Wk)
{
    __shared__ float As[32][132];   // [k][m] (col-major A), tf32
    __shared__ float Bs[64][36];    // [n][k], tf32
    const int t = threadIdx.x;
    const int warp = t >> 5;
    const int wm = warp >> 1;       // 0..3  -> m0 = wm*32
    const int wn = warp & 1;        // 0..1  -> n0 = wn*32
    const int mg0 = blockIdx.x * 128;       // global pixel (incl. batch)
    const int b = mg0 >> 12;
    const int pix0 = mg0 & 4095;

    const float* x = blockIdx.y ? kk : q;
    const float* W = blockIdx.y ? Wk : Wq;
    float* outp    = blockIdx.y ? g_pk : g_pq;
    const float* xb = x + (size_t)b * CC * HW + pix0;

    wmma::fragment<wmma::accumulator, 16, 16, 8, float> acc[2][2];
#pragma unroll
    for (int i = 0; i < 2; i++)
#pragma unroll
        for (int j = 0; j < 2; j++) wmma::fill_fragment(acc[i][j], 0.0f);

    for (int c0 = 0; c0 < CC; c0 += 32) {
#pragma unroll
        for (int i = 0; i < 4; i++) {           // As: 1024 float4
            int idx = t + i * 256;
            int r = idx >> 5, c4 = idx & 31;
            ((float4*)&As[r][0])[c4] =
                tf32x4(*(const float4*)(xb + (size_t)(c0 + r) * HW + c4 * 4));
        }
#pragma unroll
        for (int i = 0; i < 2; i++) {           // Bs: 512 float4
            int idx = t + i * 256;
            int n = idx >> 3, k4 = idx & 7;
            ((float4*)&Bs[n][0])[k4] =
                tf32x4(*(const float4*)(W + (size_t)n * CC + c0 + k4 * 4));
        }
        __syncthreads();
#pragma unroll
        for (int ks = 0; ks < 4; ks++) {
            wmma::fragment<wmma::matrix_a, 16, 16, 8, wmma::precision::tf32,
                           wmma::col_major> a[2];
            wmma::load_matrix_sync(a[0], &As[ks * 8][wm * 32], 132);
            wmma::load_matrix_sync(a[1], &As[ks * 8][wm * 32 + 16], 132);
            wmma::fragment<wmma::matrix_b, 16, 16, 8, wmma::precision::tf32,
                           wmma::col_major> bf[2];
            wmma::load_matrix_sync(bf[0], &Bs[wn * 32][ks * 8], 36);
            wmma::load_matrix_sync(bf[1], &Bs[wn * 32 + 16][ks * 8], 36);
#pragma unroll
            for (int i = 0; i < 2; i++)
#pragma unroll
                for (int j = 0; j < 2; j++)
                    wmma::mma_sync(acc[i][j], a[i], bf[j], acc[i][j]);
        }
        __syncthreads();
    }
#pragma unroll
    for (int i = 0; i < 2; i++)
#pragma unroll
        for (int j = 0; j < 2; j++)
            wmma::store_matrix_sync(
                outp + (size_t)(mg0 + wm * 32 + i * 16) * 64 + wn * 32 + j * 16,
                acc[i][j], 64, wmma::mem_row_major);
}

// ---------------------------------------------------------------------------
// v projection (no bias): 128 pixels x 128 c tile. 8 warps = 2(m:64) x 4(n:32),
// acc 4x2 frags. grid = (4 n-tiles, 256 m-tiles) so N-tiles of one m-tile are
// adjacent (x re-reads hit L2).
// ---------------------------------------------------------------------------
__global__ __launch_bounds__(256) void proj_pv(
    const float* __restrict__ v, const float* __restrict__ Wv)
{
    __shared__ float As[32][132];   // [k][m] tf32
    __shared__ float Bs[128][36];   // [n][k] tf32
    const int t = threadIdx.x;
    const int warp = t >> 5;
    const int wm = warp >> 2;       // 0..1 -> m0 = wm*64
    const int wn = warp & 3;        // 0..3 -> n0 = wn*32
    const int nt = blockIdx.x;      // n tile (128)
    const int mg0 = blockIdx.y * 128;
    const int b = mg0 >> 12;
    const int pix0 = mg0 & 4095;
    const float* xb = v + (size_t)b * CC * HW + pix0;
    const float* Wb = Wv + (size_t)(nt * 128) * CC;

    wmma::fragment<wmma::accumulator, 16, 16, 8, float> acc[4][2];
#pragma unroll
    for (int i = 0; i < 4; i++)
#pragma unroll
        for (int j = 0; j < 2; j++) wmma::fill_fragment(acc[i][j], 0.0f);

    for (int c0 = 0; c0 < CC; c0 += 32) {
#pragma unroll
        for (int i = 0; i < 4; i++) {           // As: 1024 float4
            int idx = t + i * 256;
            int r = idx >> 5, c4 = idx & 31;
            ((float4*)&As[r][0])[c4] =
                tf32x4(*(const float4*)(xb + (size_t)(c0 + r) * HW + c4 * 4));
        }
#pragma unroll
        for (int i = 0; i < 4; i++) {           // Bs: 1024 float4
            int idx = t + i * 256;
            int n = idx >> 3, k4 = idx & 7;
            ((float4*)&Bs[n][0])[k4] =
                tf32x4(*(const float4*)(Wb + (size_t)n * CC + c0 + k4 * 4));
        }
        __syncthreads();
#pragma unroll
        for (int ks = 0; ks < 4; ks++) {
            wmma::fragment<wmma::matrix_a, 16, 16, 8, wmma::precision::tf32,
                           wmma::col_major> a[4];
#pragma unroll
            for (int i = 0; i < 4; i++)
                wmma::load_matrix_sync(a[i], &As[ks * 8][wm * 64 + i * 16], 132);
            wmma::fragment<wmma::matrix_b, 16, 16, 8, wmma::precision::tf32,
                           wmma::col_major> bf[2];
#pragma unroll
            for (int j = 0; j < 2; j++)
                wmma::load_matrix_sync(bf[j], &Bs[wn * 32 + j * 16][ks * 8], 36);
#pragma unroll
            for (int i = 0; i < 4; i++)
#pragma unroll
                for (int j = 0; j < 2; j++)
                    wmma::mma_sync(acc[i][j], a[i], bf[j], acc[i][j]);
        }
        __syncthreads();
    }
#pragma unroll
    for (int i = 0; i < 4; i++)
#pragma unroll
        for (int j = 0; j < 2; j++)
            wmma::store_matrix_sync(
                g_pv + (size_t)(mg0 + wm * 64 + i * 16) * CC
                     + nt * 128 + wn * 32 + j * 16,
                acc[i][j], CC, wmma::mem_row_major);
}

// ---------------------------------------------------------------------------
// Attention scores, fp32 FFMA (bias added here since projections are raw).
// blockIdx.z = mode. mode 0: per (b,w) S[h][g]; mode 1: per (b,h) S[w][f].
// ---------------------------------------------------------------------------
__global__ __launch_bounds__(256) void scores_kernel(
    const float* __restrict__ bq, const float* __restrict__ bk)
{
    __shared__ float As[64][65];
    __shared__ float Bs[64][65];
    const int t = threadIdx.x;
    const int q = blockIdx.x;
    const int b = blockIdx.y;
    const int mode = blockIdx.z;

    size_t base; int rs;
    if (mode == 0) { base = ((size_t)b * HW + q) * 64;      rs = 4096; }
    else           { base = ((size_t)b * HW + q * 64) * 64; rs = 64;   }

    for (int idx = t; idx < 4096; idx += 256) {
        int i = idx >> 6, c = idx & 63;
        As[i][c] = g_pq[base + (size_t)i * rs + c] + bq[c];
        Bs[i][c] = g_pk[base + (size_t)i * rs + c] + bk[c];
    }
    __syncthreads();

    const int i0 = (t & 15) * 4;
    const int j0 = (t >> 4) * 4;
    float acc[4][4];
#pragma unroll
    for (int ii = 0; ii < 4; ii++)
#pragma unroll
        for (int jj = 0; jj < 4; jj++) acc[ii][jj] = 0.f;

#pragma unroll 8
    for (int c = 0; c < 64; c++) {
        float a[4], bb[4];
#pragma unroll
        for (int k = 0; k < 4; k++) { a[k] = As[i0 + k][c]; bb[k] = Bs[j0 + k][c]; }
#pragma unroll
        for (int ii = 0; ii < 4; ii++)
#pragma unroll
            for (int jj = 0; jj < 4; jj++) acc[ii][jj] += a[ii] * bb[jj];
    }

#pragma unroll
    for (int ii = 0; ii < 4; ii++) {
#pragma unroll
        for (int jj = 0; jj < 4; jj++) {
            int i = i0 + ii, j = j0 + jj;
            float v = acc[ii][jj];
            size_t o;
            if (mode == 0) {
                if (i == j) v = -1e30f;
                o = (((size_t)b * HH + i) * WW + q) * 128 + j;
            } else {
                o = (((size_t)b * HH + q) * WW + i) * 128 + 64 + j;
            }
            g_att[o] = v;
        }
    }
}

// ---------------------------------------------------------------------------
// Softmax over 128 concatenated logits; one warp per row.
// ---------------------------------------------------------------------------
__global__ __launch_bounds__(256) void softmax_kernel()
{
    const int r    = (blockIdx.x * 256 + threadIdx.x) >> 5;
    const int lane = threadIdx.x & 31;
    float4* row = (float4*)(g_att + (size_t)r * 128);
    float4 v = row[lane];
    float m = fmaxf(fmaxf(v.x, v.y), fmaxf(v.z, v.w));
#pragma unroll
    for (int o = 16; o > 0; o >>= 1) m = fmaxf(m, __shfl_xor_sync(0xffffffffu, m, o));
    v.x = __expf(v.x - m); v.y = __expf(v.y - m);
    v.z = __expf(v.z - m); v.w = __expf(v.w - m);
    float s = v.x + v.y + v.z + v.w;
#pragma unroll
    for (int o = 16; o > 0; o >>= 1) s += __shfl_xor_sync(0xffffffffu, s, o);
    float inv = 1.0f / s;
    v.x *= inv; v.y *= inv; v.z *= inv; v.w *= inv;
    row[lane] = v;
}

// ---------------------------------------------------------------------------
// tmpH[b,w,h,c] = sum_g attH[b,h,w,g] * pv[b,pix(g,w),c]   (raw pv, no bias)
// Dynamic smem: Att[64][68] + Ps[64][132]. 8 warps = 4(h:16) x 2(c:64).
// ---------------------------------------------------------------------------
__global__ __launch_bounds__(256) void tmph_wmma()
{
    extern __shared__ float sm[];
    float (*Att)[68] = (float(*)[68])sm;              // [h][g] tf32
    float (*Ps)[132] = (float(*)[132])(sm + 64 * 68); // [g][c] tf32
    const int t = threadIdx.x, w = blockIdx.x, b = blockIdx.y;
    const int warp = t >> 5;
    const int wh = warp >> 1;       // h tile (16)
    const int wc = warp & 1;        // c half (64)

#pragma unroll
    for (int i = 0; i < 4; i++) {   // Att: 1024 float4
        int idx = t + i * 256;
        int h = idx >> 4, g4 = idx & 15;
        ((float4*)&Att[h][0])[g4] = tf32x4(
            *(const float4*)(g_att + (((size_t)b * HH + h) * WW + w) * 128 + g4 * 4));
    }

    for (int c0 = 0; c0 < CC; c0 += 128) {
        __syncthreads();
#pragma unroll
        for (int i = 0; i < 8; i++) {   // Ps: 2048 float4
            int idx = t + i * 256;
            int g = idx >> 5, c4 = idx & 31;
            ((float4*)&Ps[g][0])[c4] = tf32x4(
                *(const float4*)(g_pv + ((size_t)b * HW + g * WW + w) * CC + c0 + c4 * 4));
        }
        __syncthreads();

        wmma::fragment<wmma::accumulator, 16, 16, 8, float> acc[4];
#pragma unroll
        for (int i = 0; i < 4; i++) wmma::fill_fragment(acc[i], 0.0f);
#pragma unroll
        for (int ks = 0; ks < 8; ks++) {
            wmma::fragment<wmma::matrix_a, 16, 16, 8, wmma::precision::tf32,
                           wmma::row_major> a;
            wmma::load_matrix_sync(a, &Att[wh * 16][ks * 8], 68);
#pragma unroll
            for (int ci = 0; ci < 4; ci++) {
                wmma::fragment<wmma::matrix_b, 16, 16, 8, wmma::precision::tf32,
                               wmma::row_major> bf;
                wmma::load_matrix_sync(bf, &Ps[ks * 8][wc * 64 + ci * 16], 132);
                wmma::mma_sync(acc[ci], a, bf, acc[ci]);
            }
        }
        float* dst = g_tmpH + (((size_t)b * WW + w) * HH + wh * 16) * CC + c0;
#pragma unroll
        for (int ci = 0; ci < 4; ci++)
            wmma::store_matrix_sync(dst + wc * 64 + ci * 16, acc[ci], CC,
                                    wmma::mem_row_major);
    }
}

// ---------------------------------------------------------------------------
// Final per (b,h): Sw[w][c] = sum_f attW[b,h,w,f] * pv[b,pix(h,f),c];
// out[b,c,h,w] = value + gamma * (Sw + tmpH[b,w,h,c] + bv[c])
// ---------------------------------------------------------------------------
__global__ __launch_bounds__(256) void final_wmma(
    const float* __restrict__ value, const float* __restrict__ bv,
    const float* __restrict__ gamma, float* __restrict__ out)
{
    extern __shared__ float sm[];
    float (*Att)[68] = (float(*)[68])sm;              // [w][f] tf32
    float (*Ps)[132] = (float(*)[132])(sm + 64 * 68); // [f][c] tf32 -> reused as Osm[w][c]
    const int t = threadIdx.x, h = blockIdx.x, b = blockIdx.y;
    const int warp = t >> 5;
    const int ww = warp >> 1;       // w tile (16)
    const int wc = warp & 1;        // c half (64)
    const float gm = gamma[0];

#pragma unroll
    for (int i = 0; i < 4; i++) {
        int idx = t + i * 256;
        int w = idx >> 4, f4 = idx & 15;
        ((float4*)&Att[w][0])[f4] = tf32x4(
            *(const float4*)(g_att + (((size_t)b * HH + w) * WW) * 0
                             + (((size_t)b * HH + h) * WW + w) * 128 + 64 + f4 * 4));
    }

    const int w4 = t & 15;          // epilogue: 4 consecutive w
    const int cB = t >> 4;          // epilogue: 8 consecutive c

    for (int c0 = 0; c0 < CC; c0 += 128) {
        __syncthreads();
#pragma unroll
        for (int i = 0; i < 8; i++) {
            int idx = t + i * 256;
            int f = idx >> 5, c4 = idx & 31;
            ((float4*)&Ps[f][0])[c4] = tf32x4(
                *(const float4*)(g_pv + ((size_t)b * HW + h * WW + f) * CC + c0 + c4 * 4));
        }
        __syncthreads();

        wmma::fragment<wmma::accumulator, 16, 16, 8, float> acc[4];
#pragma unroll
        for (int i = 0; i < 4; i++) wmma::fill_fragment(acc[i], 0.0f);
#pragma unroll
        for (int ks = 0; ks < 8; ks++) {
            wmma::fragment<wmma::matrix_a, 16, 16, 8, wmma::precision::tf32,
                           wmma::row_major> a;
            wmma::load_matrix_sync(a, &Att[ww * 16][ks * 8], 68);
#pragma unroll
            for (int ci = 0; ci < 4; ci++) {
                wmma::fragment<wmma::matrix_b, 16, 16, 8, wmma::precision::tf32,
                               wmma::row_major> bf;
                wmma::load_matrix_sync(bf, &Ps[ks * 8][wc * 64 + ci * 16], 132);
                wmma::mma_sync(acc[ci], a, bf, acc[ci]);
            }
        }
        __syncthreads();            // all reads of Ps done
#pragma unroll
        for (int ci = 0; ci < 4; ci++)
            wmma::store_matrix_sync(&Ps[ww * 16][wc * 64 + ci * 16], acc[ci], 132,
                                    wmma::mem_row_major);   // Osm[w][c]
        __syncthreads();

        // Epilogue: out = value + gm*(Osm + tmpH + bv)
        float th[4][8];
#pragma unroll
        for (int wi = 0; wi < 4; wi++) {
            const float* tp = g_tmpH +
                (((size_t)b * WW + w4 * 4 + wi) * HH + h) * CC + c0 + cB * 8;
            float4 u0 = *(const float4*)tp;
            float4 u1 = *(const float4*)(tp + 4);
            th[wi][0] = u0.x; th[wi][1] = u0.y; th[wi][2] = u0.z; th[wi][3] = u0.w;
            th[wi][4] = u1.x; th[wi][5] = u1.y; th[wi][6] = u1.z; th[wi][7] = u1.w;
        }
#pragma unroll
        for (int ci = 0; ci < 8; ci++) {
            int c = c0 + cB * 8 + ci;
            float bvv = bv[c];
            size_t vbase = (((size_t)b * CC + c) * HH + h) * WW;
            float4 vv = ((const float4*)(value + vbase))[w4];
            float4 ov;
            ov.x = vv.x + gm * (Ps[w4 * 4 + 0][cB * 8 + ci] + th[0][ci] + bvv);
            ov.y = vv.y + gm * (Ps[w4 * 4 + 1][cB * 8 + ci] + th[1][ci] + bvv);
            ov.z = vv.z + gm * (Ps[w4 * 4 + 2][cB * 8 + ci] + th[2][ci] + bvv);
            ov.w = vv.w + gm * (Ps[w4 * 4 + 3][cB * 8 + ci] + th[3][ci] + bvv);
            ((float4*)(out + vbase))[w4] = ov;
        }
    }
}

// ---------------------------------------------------------------------------
#define SMEM_TF ((64 * 68 + 64 * 132) * 4)   // 51200 bytes

extern "C" void kernel_launch(void* const* d_in, const int* in_sizes, int n_in,
                              void* d_out, int out_size)
{
    (void)in_sizes; (void)n_in; (void)out_size;
    const float* query = (const float*)d_in[0];
    const float* key_t = (const float*)d_in[1];
    const float* value = (const float*)d_in[2];
    const float* Wq    = (const float*)d_in[3];
    const float* bq    = (const float*)d_in[4];
    const float* Wk    = (const float*)d_in[5];
    const float* bk    = (const float*)d_in[6];
    const float* Wv    = (const float*)d_in[7];
    const float* bv    = (const float*)d_in[8];
    const float* gamma = (const float*)d_in[9];
    float* out = (float*)d_out;

    cudaFuncSetAttribute(tmph_wmma,  cudaFuncAttributeMaxDynamicSharedMemorySize, SMEM_TF);
    cudaFuncSetAttribute(final_wmma, cudaFuncAttributeMaxDynamicSharedMemorySize, SMEM_TF);

    proj_qk<<<dim3(256, 2), 256>>>(query, Wq, key_t, Wk);
    proj_pv<<<dim3(4, 256), 256>>>(value, Wv);

    scores_kernel<<<dim3(64, BB, 2), 256>>>(bq, bk);
    softmax_kernel<<<4096, 256>>>();

    tmph_wmma<<<dim3(WW, BB), 256, SMEM_TF>>>();
    final_wmma<<<dim3(HH, BB), 256, SMEM_TF>>>(value, bv, gamma, out);
}

// round 10
// speedup vs baseline: 1.4286x; 1.0153x over previous
#include <cuda_runtime.h>
#include <cstdint>
#include <mma.h>
#include <math.h>

using namespace nvcuda;

#define BB 8
#define CC 512
#define HH 64
#define WW 64
#define HW 4096            // HH*WW

// Scratch (allocation-free: __device__ globals). Projections stored WITHOUT bias.
__device__ float g_pq[BB * HW * 64];              // [b, pix(h*64+w), o]
__device__ float g_pk[BB * HW * 64];              // [b, pix, o]
__device__ float g_pv[(size_t)BB * HW * CC];      // [b, pix, c]
__device__ float g_att[(size_t)BB * HW * 128];    // [b, h, w, 0:64=attH | 64:128=attW]
__device__ float g_tmpH[(size_t)BB * HW * CC];    // [b, w, h, c]

// ---- cp.async helpers -----------------------------------------------------
__device__ __forceinline__ unsigned sptr(const void* p) {
    return (unsigned)__cvta_generic_to_shared(p);
}
__device__ __forceinline__ void cpa16(unsigned s, const void* g) {
    asm volatile("cp.async.cg.shared.global [%0], [%1], 16;\n" :: "r"(s), "l"(g));
}
#define CP_COMMIT() asm volatile("cp.async.commit_group;\n" ::: "memory")
#define CP_WAIT(n)  asm volatile("cp.async.wait_group %0;\n" :: "n"(n) : "memory")

// ---------------------------------------------------------------------------
// q/k projection (no bias): out[b,pix,o] = sum_c W[o,c] * x[b,c,pix]
// Block: 128 pixels x 64 o. 8 warps = 4(m:32) x 2(n:32), acc 2x2 frags.
// 2-stage cp.async pipeline over 16 K-chunks of 32.
// ---------------------------------------------------------------------------
__global__ __launch_bounds__(256) void proj_qk(
    const float* __restrict__ q, const float* __restrict__ Wq,
    const float* __restrict__ kk, const float* __restrict__ Wk)
{
    extern __shared__ float sm[];
    float (*As)[32][132] = (float(*)[32][132])sm;                 // [buf][k][m]
    float (*Bs)[64][36]  = (float(*)[64][36])(sm + 2 * 32 * 132); // [buf][n][k]

    const int t = threadIdx.x;
    const int warp = t >> 5;
    const int wm = warp >> 1;
    const int wn = warp & 1;
    const int mg0 = blockIdx.x * 128;
    const int b = mg0 >> 12;
    const int pix0 = mg0 & 4095;

    const float* x = blockIdx.y ? kk : q;
    const float* W = blockIdx.y ? Wk : Wq;
    float* outp    = blockIdx.y ? g_pk : g_pq;
    const float* xb = x + (size_t)b * CC * HW + pix0;

    wmma::fragment<wmma::accumulator, 16, 16, 8, float> acc[2][2];
#pragma unroll
    for (int i = 0; i < 2; i++)
#pragma unroll
        for (int j = 0; j < 2; j++) wmma::fill_fragment(acc[i][j], 0.0f);

    auto stage = [&](int buf, int c0) {
#pragma unroll
        for (int i = 0; i < 4; i++) {               // As: 1024 float4
            int idx = t + i * 256;
            int r = idx >> 5, c4 = idx & 31;
            cpa16(sptr(&As[buf][r][c4 * 4]), xb + (size_t)(c0 + r) * HW + c4 * 4);
        }
#pragma unroll
        for (int i = 0; i < 2; i++) {               // Bs: 512 float4
            int idx = t + i * 256;
            int n = idx >> 3, k4 = idx & 7;
            cpa16(sptr(&Bs[buf][n][k4 * 4]), W + (size_t)n * CC + c0 + k4 * 4);
        }
        CP_COMMIT();
    };

    stage(0, 0);
    for (int kc = 0; kc < 16; kc++) {
        const int cur = kc & 1;
        if (kc < 15) { stage(cur ^ 1, (kc + 1) * 32); CP_WAIT(1); }
        else         { CP_WAIT(0); }
        __syncthreads();
#pragma unroll
        for (int ks = 0; ks < 4; ks++) {
            wmma::fragment<wmma::matrix_a, 16, 16, 8, wmma::precision::tf32,
                           wmma::col_major> a[2];
            wmma::load_matrix_sync(a[0], &As[cur][ks * 8][wm * 32], 132);
            wmma::load_matrix_sync(a[1], &As[cur][ks * 8][wm * 32 + 16], 132);
            wmma::fragment<wmma::matrix_b, 16, 16, 8, wmma::precision::tf32,
                           wmma::col_major> bf[2];
            wmma::load_matrix_sync(bf[0], &Bs[cur][wn * 32][ks * 8], 36);
            wmma::load_matrix_sync(bf[1], &Bs[cur][wn * 32 + 16][ks * 8], 36);
#pragma unroll
            for (int i = 0; i < 2; i++)
#pragma unroll
                for (int j = 0; j < 2; j++)
                    wmma::mma_sync(acc[i][j], a[i], bf[j], acc[i][j]);
        }
        __syncthreads();
    }
#pragma unroll
    for (int i = 0; i < 2; i++)
#pragma unroll
        for (int j = 0; j < 2; j++)
            wmma::store_matrix_sync(
                outp + (size_t)(mg0 + wm * 32 + i * 16) * 64 + wn * 32 + j * 16,
                acc[i][j], 64, wmma::mem_row_major);
}

// ---------------------------------------------------------------------------
// v projection (no bias): 128 pixels x 128 c tile. 8 warps = 2(m:64) x 4(n:32),
// acc 4x2 frags. 2-stage cp.async pipeline.
// ---------------------------------------------------------------------------
__global__ __launch_bounds__(256) void proj_pv(
    const float* __restrict__ v, const float* __restrict__ Wv)
{
    extern __shared__ float sm[];
    float (*As)[32][132] = (float(*)[32][132])sm;
    float (*Bs)[128][36] = (float(*)[128][36])(sm + 2 * 32 * 132);

    const int t = threadIdx.x;
    const int warp = t >> 5;
    const int wm = warp >> 2;
    const int wn = warp & 3;
    const int nt = blockIdx.x;
    const int mg0 = blockIdx.y * 128;
    const int b = mg0 >> 12;
    const int pix0 = mg0 & 4095;
    const float* xb = v + (size_t)b * CC * HW + pix0;
    const float* Wb = Wv + (size_t)(nt * 128) * CC;

    wmma::fragment<wmma::accumulator, 16, 16, 8, float> acc[4][2];
#pragma unroll
    for (int i = 0; i < 4; i++)
#pragma unroll
        for (int j = 0; j < 2; j++) wmma::fill_fragment(acc[i][j], 0.0f);

    auto stage = [&](int buf, int c0) {
#pragma unroll
        for (int i = 0; i < 4; i++) {
            int idx = t + i * 256;
            int r = idx >> 5, c4 = idx & 31;
            cpa16(sptr(&As[buf][r][c4 * 4]), xb + (size_t)(c0 + r) * HW + c4 * 4);
        }
#pragma unroll
        for (int i = 0; i < 4; i++) {
            int idx = t + i * 256;
            int n = idx >> 3, k4 = idx & 7;
            cpa16(sptr(&Bs[buf][n][k4 * 4]), Wb + (size_t)n * CC + c0 + k4 * 4);
        }
        CP_COMMIT();
    };

    stage(0, 0);
    for (int kc = 0; kc < 16; kc++) {
        const int cur = kc & 1;
        if (kc < 15) { stage(cur ^ 1, (kc + 1) * 32); CP_WAIT(1); }
        else         { CP_WAIT(0); }
        __syncthreads();
#pragma unroll
        for (int ks = 0; ks < 4; ks++) {
            wmma::fragment<wmma::matrix_a, 16, 16, 8, wmma::precision::tf32,
                           wmma::col_major> a[4];
#pragma unroll
            for (int i = 0; i < 4; i++)
                wmma::load_matrix_sync(a[i], &As[cur][ks * 8][wm * 64 + i * 16], 132);
            wmma::fragment<wmma::matrix_b, 16, 16, 8, wmma::precision::tf32,
                           wmma::col_major> bf[2];
#pragma unroll
            for (int j = 0; j < 2; j++)
                wmma::load_matrix_sync(bf[j], &Bs[cur][wn * 32 + j * 16][ks * 8], 36);
#pragma unroll
            for (int i = 0; i < 4; i++)
#pragma unroll
                for (int j = 0; j < 2; j++)
                    wmma::mma_sync(acc[i][j], a[i], bf[j], acc[i][j]);
        }
        __syncthreads();
    }
#pragma unroll
    for (int i = 0; i < 4; i++)
#pragma unroll
        for (int j = 0; j < 2; j++)
            wmma::store_matrix_sync(
                g_pv + (size_t)(mg0 + wm * 64 + i * 16) * CC
                     + nt * 128 + wn * 32 + j * 16,
                acc[i][j], CC, wmma::mem_row_major);
}

// ---------------------------------------------------------------------------
// Attention scores, fp32 FFMA (bias added during staging). 512 threads.
// blockIdx.z = mode. mode 0: per (b,w) S[h][g] + diag mask; mode 1: per (b,h).
// ---------------------------------------------------------------------------
__global__ __launch_bounds__(512) void scores_kernel(
    const float* __restrict__ bq, const float* __restrict__ bk)
{
    __shared__ float As[64][65];
    __shared__ float Bs[64][65];
    const int t = threadIdx.x;
    const int q = blockIdx.x;
    const int b = blockIdx.y;
    const int mode = blockIdx.z;

    size_t base; int rs;
    if (mode == 0) { base = ((size_t)b * HW + q) * 64;      rs = 4096; }
    else           { base = ((size_t)b * HW + q * 64) * 64; rs = 64;   }

    for (int idx = t; idx < 4096; idx += 512) {
        int i = idx >> 6, c = idx & 63;
        As[i][c] = g_pq[base + (size_t)i * rs + c] + bq[c];
        Bs[i][c] = g_pk[base + (size_t)i * rs + c] + bk[c];
    }
    __syncthreads();

    const int i0 = (t & 15) * 4;
    const int j0 = (t >> 4) * 2;
    float acc[4][2];
#pragma unroll
    for (int ii = 0; ii < 4; ii++) { acc[ii][0] = 0.f; acc[ii][1] = 0.f; }

#pragma unroll 8
    for (int c = 0; c < 64; c++) {
        float a0 = As[i0 + 0][c], a1 = As[i0 + 1][c];
        float a2 = As[i0 + 2][c], a3 = As[i0 + 3][c];
        float b0 = Bs[j0 + 0][c], b1 = Bs[j0 + 1][c];
        acc[0][0] += a0 * b0; acc[0][1] += a0 * b1;
        acc[1][0] += a1 * b0; acc[1][1] += a1 * b1;
        acc[2][0] += a2 * b0; acc[2][1] += a2 * b1;
        acc[3][0] += a3 * b0; acc[3][1] += a3 * b1;
    }

#pragma unroll
    for (int ii = 0; ii < 4; ii++) {
#pragma unroll
        for (int jj = 0; jj < 2; jj++) {
            int i = i0 + ii, j = j0 + jj;
            float v = acc[ii][jj];
            size_t o;
            if (mode == 0) {
                if (i == j) v = -1e30f;
                o = (((size_t)b * HH + i) * WW + q) * 128 + j;
            } else {
                o = (((size_t)b * HH + q) * WW + i) * 128 + 64 + j;
            }
            g_att[o] = v;
        }
    }
}

// ---------------------------------------------------------------------------
// Softmax over 128 concatenated logits; one warp per row.
// ---------------------------------------------------------------------------
__global__ __launch_bounds__(256) void softmax_kernel()
{
    const int r    = (blockIdx.x * 256 + threadIdx.x) >> 5;
    const int lane = threadIdx.x & 31;
    float4* row = (float4*)(g_att + (size_t)r * 128);
    float4 v = row[lane];
    float m = fmaxf(fmaxf(v.x, v.y), fmaxf(v.z, v.w));
#pragma unroll
    for (int o = 16; o > 0; o >>= 1) m = fmaxf(m, __shfl_xor_sync(0xffffffffu, m, o));
    v.x = __expf(v.x - m); v.y = __expf(v.y - m);
    v.z = __expf(v.z - m); v.w = __expf(v.w - m);
    float s = v.x + v.y + v.z + v.w;
#pragma unroll
    for (int o = 16; o > 0; o >>= 1) s += __shfl_xor_sync(0xffffffffu, s, o);
    float inv = 1.0f / s;
    v.x *= inv; v.y *= inv; v.z *= inv; v.w *= inv;
    row[lane] = v;
}

// ---------------------------------------------------------------------------
// tmpH[b,w,h,c] = sum_g attH[b,h,w,g] * pv[b,pix(g,w),c]
// Pipeline pv chunks (c0 += 128, 4 chunks) with cp.async. 8 warps = 4(h) x 2(c:64).
// ---------------------------------------------------------------------------
__global__ __launch_bounds__(256) void tmph_wmma()
{
    extern __shared__ float sm[];
    float (*Att)[68] = (float(*)[68])sm;                       // [h][g]
    float (*Ps)[64][132] = (float(*)[64][132])(sm + 64 * 68);  // [buf][g][c]
    const int t = threadIdx.x, w = blockIdx.x, b = blockIdx.y;
    const int warp = t >> 5;
    const int wh = warp >> 1;
    const int wc = warp & 1;

    auto stage = [&](int buf, int c0) {
#pragma unroll
        for (int i = 0; i < 8; i++) {          // 2048 float4
            int idx = t + i * 256;
            int g = idx >> 5, c4 = idx & 31;
            cpa16(sptr(&Ps[buf][g][c4 * 4]),
                  g_pv + ((size_t)b * HW + g * WW + w) * CC + c0 + c4 * 4);
        }
        CP_COMMIT();
    };

    stage(0, 0);
#pragma unroll
    for (int i = 0; i < 4; i++) {              // Att: 1024 float4
        int idx = t + i * 256;
        int h = idx >> 4, g4 = idx & 15;
        ((float4*)&Att[h][0])[g4] =
            *(const float4*)(g_att + (((size_t)b * HH + h) * WW + w) * 128 + g4 * 4);
    }

    for (int kc = 0; kc < 4; kc++) {
        const int cur = kc & 1;
        const int c0 = kc * 128;
        if (kc < 3) { stage(cur ^ 1, c0 + 128); CP_WAIT(1); }
        else        { CP_WAIT(0); }
        __syncthreads();

        wmma::fragment<wmma::accumulator, 16, 16, 8, float> acc[4];
#pragma unroll
        for (int i = 0; i < 4; i++) wmma::fill_fragment(acc[i], 0.0f);
#pragma unroll
        for (int ks = 0; ks < 8; ks++) {
            wmma::fragment<wmma::matrix_a, 16, 16, 8, wmma::precision::tf32,
                           wmma::row_major> a;
            wmma::load_matrix_sync(a, &Att[wh * 16][ks * 8], 68);
#pragma unroll
            for (int ci = 0; ci < 4; ci++) {
                wmma::fragment<wmma::matrix_b, 16, 16, 8, wmma::precision::tf32,
                               wmma::row_major> bf;
                wmma::load_matrix_sync(bf, &Ps[cur][ks * 8][wc * 64 + ci * 16], 132);
                wmma::mma_sync(acc[ci], a, bf, acc[ci]);
            }
        }
        float* dst = g_tmpH + (((size_t)b * WW + w) * HH + wh * 16) * CC + c0;
#pragma unroll
        for (int ci = 0; ci < 4; ci++)
            wmma::store_matrix_sync(dst + wc * 64 + ci * 16, acc[ci], CC,
                                    wmma::mem_row_major);
        __syncthreads();
    }
}

// ---------------------------------------------------------------------------
// Final per (b,h): Sw[w][c] = sum_f attW[b,h,w,f] * pv[b,pix(h,f),c];
// out[b,c,h,w] = value + gamma * (Sw + tmpH[b,w,h,c] + bv[c])
// Osm is [64][132]: 128 c-columns per chunk + pad (fixes R8 OOB smem write).
// ---------------------------------------------------------------------------
__global__ __launch_bounds__(256) void final_wmma(
    const float* __restrict__ value, const float* __restrict__ bv,
    const float* __restrict__ gamma, float* __restrict__ out)
{
    extern __shared__ float sm[];
    float (*Att)[68] = (float(*)[68])sm;                        // [w][f]
    float (*Ps)[64][132] = (float(*)[64][132])(sm + 64 * 68);   // [buf][f][c]
    float (*Osm)[132] = (float(*)[132])(sm + 64 * 68 + 2 * 64 * 132); // [w][c0..c127]
    const int t = threadIdx.x, h = blockIdx.x, b = blockIdx.y;
    const int warp = t >> 5;
    const int ww = warp >> 1;
    const int wc = warp & 1;
    const float gm = gamma[0];

    auto stage = [&](int buf, int c0) {
#pragma unroll
        for (int i = 0; i < 8; i++) {
            int idx = t + i * 256;
            int f = idx >> 5, c4 = idx & 31;
            cpa16(sptr(&Ps[buf][f][c4 * 4]),
                  g_pv + ((size_t)b * HW + h * WW + f) * CC + c0 + c4 * 4);
        }
        CP_COMMIT();
    };

    stage(0, 0);
#pragma unroll
    for (int i = 0; i < 4; i++) {
        int idx = t + i * 256;
        int w = idx >> 4, f4 = idx & 15;
        ((float4*)&Att[w][0])[f4] = *(const float4*)(
            g_att + (((size_t)b * HH + h) * WW + w) * 128 + 64 + f4 * 4);
    }

    const int w4 = t & 15;          // epilogue: 4 consecutive w
    const int cB = t >> 4;          // epilogue: 8 consecutive c

    for (int kc = 0; kc < 4; kc++) {
        const int cur = kc & 1;
        const int c0 = kc * 128;
        if (kc < 3) { stage(cur ^ 1, c0 + 128); CP_WAIT(1); }
        else        { CP_WAIT(0); }
        __syncthreads();   // Ps[cur] ready; orders prior epilogue's Osm reads too

        wmma::fragment<wmma::accumulator, 16, 16, 8, float> acc[4];
#pragma unroll
        for (int i = 0; i < 4; i++) wmma::fill_fragment(acc[i], 0.0f);
#pragma unroll
        for (int ks = 0; ks < 8; ks++) {
            wmma::fragment<wmma::matrix_a, 16, 16, 8, wmma::precision::tf32,
                           wmma::row_major> a;
            wmma::load_matrix_sync(a, &Att[ww * 16][ks * 8], 68);
#pragma unroll
            for (int ci = 0; ci < 4; ci++) {
                wmma::fragment<wmma::matrix_b, 16, 16, 8, wmma::precision::tf32,
                               wmma::row_major> bf;
                wmma::load_matrix_sync(bf, &Ps[cur][ks * 8][wc * 64 + ci * 16], 132);
                wmma::mma_sync(acc[ci], a, bf, acc[ci]);
            }
        }
#pragma unroll
        for (int ci = 0; ci < 4; ci++)
            wmma::store_matrix_sync(&Osm[ww * 16][wc * 64 + ci * 16], acc[ci], 132,
                                    wmma::mem_row_major);   // Osm[w][c in 0..127]
        __syncthreads();

        // Epilogue: out = value + gm*(Osm + tmpH + bv)
        float th[4][8];
#pragma unroll
        for (int wi = 0; wi < 4; wi++) {
            const float* tp = g_tmpH +
                (((size_t)b * WW + w4 * 4 + wi) * HH + h) * CC + c0 + cB * 8;
            float4 u0 = *(const float4*)tp;
            float4 u1 = *(const float4*)(tp + 4);
            th[wi][0] = u0.x; th[wi][1] = u0.y; th[wi][2] = u0.z; th[wi][3] = u0.w;
            th[wi][4] = u1.x; th[wi][5] = u1.y; th[wi][6] = u1.z; th[wi][7] = u1.w;
        }
#pragma unroll
        for (int ci = 0; ci < 8; ci++) {
            int c = c0 + cB * 8 + ci;
            float bvv = bv[c];
            size_t vbase = (((size_t)b * CC + c) * HH + h) * WW;
            float4 vv = ((const float4*)(value + vbase))[w4];
            float4 ov;
            ov.x = vv.x + gm * (Osm[w4 * 4 + 0][cB * 8 + ci] + th[0][ci] + bvv);
            ov.y = vv.y + gm * (Osm[w4 * 4 + 1][cB * 8 + ci] + th[1][ci] + bvv);
            ov.z = vv.z + gm * (Osm[w4 * 4 + 2][cB * 8 + ci] + th[2][ci] + bvv);
            ov.w = vv.w + gm * (Osm[w4 * 4 + 3][cB * 8 + ci] + th[3][ci] + bvv);
            ((float4*)(out + vbase))[w4] = ov;
        }
        __syncthreads();
    }
}

// ---------------------------------------------------------------------------
#define SMEM_QK  ((2 * 32 * 132 + 2 * 64 * 36) * 4)                  // 52224
#define SMEM_PV  ((2 * 32 * 132 + 2 * 128 * 36) * 4)                 // 70656
#define SMEM_TH  ((64 * 68 + 2 * 64 * 132) * 4)                      // 84992
#define SMEM_FN  ((64 * 68 + 2 * 64 * 132 + 64 * 132) * 4)           // 118784

extern "C" void kernel_launch(void* const* d_in, const int* in_sizes, int n_in,
                              void* d_out, int out_size)
{
    (void)in_sizes; (void)n_in; (void)out_size;
    const float* query = (const float*)d_in[0];
    const float* key_t = (const float*)d_in[1];
    const float* value = (const float*)d_in[2];
    const float* Wq    = (const float*)d_in[3];
    const float* bq    = (const float*)d_in[4];
    const float* Wk    = (const float*)d_in[5];
    const float* bk    = (const float*)d_in[6];
    const float* Wv    = (const float*)d_in[7];
    const float* bv    = (const float*)d_in[8];
    const float* gamma = (const float*)d_in[9];
    float* out = (float*)d_out;

    cudaFuncSetAttribute(proj_qk,    cudaFuncAttributeMaxDynamicSharedMemorySize, SMEM_QK);
    cudaFuncSetAttribute(proj_pv,    cudaFuncAttributeMaxDynamicSharedMemorySize, SMEM_PV);
    cudaFuncSetAttribute(tmph_wmma,  cudaFuncAttributeMaxDynamicSharedMemorySize, SMEM_TH);
    cudaFuncSetAttribute(final_wmma, cudaFuncAttributeMaxDynamicSharedMemorySize, SMEM_FN);

    proj_qk<<<dim3(256, 2), 256, SMEM_QK>>>(query, Wq, key_t, Wk);
    proj_pv<<<dim3(4, 256), 256, SMEM_PV>>>(value, Wv);

    scores_kernel<<<dim3(64, BB, 2), 512>>>(bq, bk);
    softmax_kernel<<<4096, 256>>>();

    tmph_wmma<<<dim3(WW, BB), 256, SMEM_TH>>>();
    final_wmma<<<dim3(HH, BB), 256, SMEM_FN>>>(value, bv, gamma, out);
}

// round 14
// speedup vs baseline: 1.5012x; 1.0508x over previous
#include <cuda_runtime.h>
#include <cstdint>
#include <mma.h>
#include <math.h>

using namespace nvcuda;

#define BB 8
#define CC 512
#define HH 64
#define WW 64
#define HW 4096            // HH*WW

// Scratch (allocation-free: __device__ globals). Projections stored WITHOUT bias.
__device__ float g_pq[BB * HW * 64];              // [b, pix(h*64+w), o]
__device__ float g_pk[BB * HW * 64];              // [b, pix, o]
__device__ float g_pv[(size_t)BB * HW * CC];      // [b, pix, c]
__device__ float g_att[(size_t)BB * HW * 128];    // [b, h, w, 0:64=attH | 64:128=attW]
__device__ float g_tmpH[(size_t)BB * HW * CC];    // [b, w, h, c]

// ---- cp.async helpers -----------------------------------------------------
__device__ __forceinline__ unsigned sptr(const void* p) {
    return (unsigned)__cvta_generic_to_shared(p);
}
__device__ __forceinline__ void cpa16(unsigned s, const void* g) {
    asm volatile("cp.async.cg.shared.global [%0], [%1], 16;\n" :: "r"(s), "l"(g));
}
#define CP_COMMIT() asm volatile("cp.async.commit_group;\n" ::: "memory")
#define CP_WAIT(n)  asm volatile("cp.async.wait_group %0;\n" :: "n"(n) : "memory")

// ---------------------------------------------------------------------------
// q/k projection (no bias): out[b,pix,o] = sum_c W[o,c] * x[b,c,pix]
// Block: 128 pixels x 64 o. 8 warps = 4(m:32) x 2(n:32), acc 2x2 frags.
// 2-stage cp.async pipeline over 16 K-chunks of 32.  2 CTAs/SM.
// ---------------------------------------------------------------------------
__global__ __launch_bounds__(256, 2) void proj_qk(
    const float* __restrict__ q, const float* __restrict__ Wq,
    const float* __restrict__ kk, const float* __restrict__ Wk)
{
    extern __shared__ float sm[];
    float (*As)[32][132] = (float(*)[32][132])sm;                 // [buf][k][m]
    float (*Bs)[64][36]  = (float(*)[64][36])(sm + 2 * 32 * 132); // [buf][n][k]

    const int t = threadIdx.x;
    const int warp = t >> 5;
    const int wm = warp >> 1;
    const int wn = warp & 1;
    const int mg0 = blockIdx.x * 128;
    const int b = mg0 >> 12;
    const int pix0 = mg0 & 4095;

    const float* x = blockIdx.y ? kk : q;
    const float* W = blockIdx.y ? Wk : Wq;
    float* outp    = blockIdx.y ? g_pk : g_pq;
    const float* xb = x + (size_t)b * CC * HW + pix0;

    wmma::fragment<wmma::accumulator, 16, 16, 8, float> acc[2][2];
#pragma unroll
    for (int i = 0; i < 2; i++)
#pragma unroll
        for (int j = 0; j < 2; j++) wmma::fill_fragment(acc[i][j], 0.0f);

    auto stage = [&](int buf, int c0) {
#pragma unroll
        for (int i = 0; i < 4; i++) {               // As: 1024 float4
            int idx = t + i * 256;
            int r = idx >> 5, c4 = idx & 31;
            cpa16(sptr(&As[buf][r][c4 * 4]), xb + (size_t)(c0 + r) * HW + c4 * 4);
        }
#pragma unroll
        for (int i = 0; i < 2; i++) {               // Bs: 512 float4
            int idx = t + i * 256;
            int n = idx >> 3, k4 = idx & 7;
            cpa16(sptr(&Bs[buf][n][k4 * 4]), W + (size_t)n * CC + c0 + k4 * 4);
        }
        CP_COMMIT();
    };

    stage(0, 0);
    for (int kc = 0; kc < 16; kc++) {
        const int cur = kc & 1;
        if (kc < 15) { stage(cur ^ 1, (kc + 1) * 32); CP_WAIT(1); }
        else         { CP_WAIT(0); }
        __syncthreads();
#pragma unroll
        for (int ks = 0; ks < 4; ks++) {
            wmma::fragment<wmma::matrix_a, 16, 16, 8, wmma::precision::tf32,
                           wmma::col_major> a[2];
            wmma::load_matrix_sync(a[0], &As[cur][ks * 8][wm * 32], 132);
            wmma::load_matrix_sync(a[1], &As[cur][ks * 8][wm * 32 + 16], 132);
            wmma::fragment<wmma::matrix_b, 16, 16, 8, wmma::precision::tf32,
                           wmma::col_major> bf[2];
            wmma::load_matrix_sync(bf[0], &Bs[cur][wn * 32][ks * 8], 36);
            wmma::load_matrix_sync(bf[1], &Bs[cur][wn * 32 + 16][ks * 8], 36);
#pragma unroll
            for (int i = 0; i < 2; i++)
#pragma unroll
                for (int j = 0; j < 2; j++)
                    wmma::mma_sync(acc[i][j], a[i], bf[j], acc[i][j]);
        }
        __syncthreads();
    }
#pragma unroll
    for (int i = 0; i < 2; i++)
#pragma unroll
        for (int j = 0; j < 2; j++)
            wmma::store_matrix_sync(
                outp + (size_t)(mg0 + wm * 32 + i * 16) * 64 + wn * 32 + j * 16,
                acc[i][j], 64, wmma::mem_row_major);
}

// ---------------------------------------------------------------------------
// v projection (no bias): 128 pixels x 128 c tile. 8 warps = 2(m:64) x 4(n:32),
// acc 4x2 frags. 2-stage cp.async pipeline.  2 CTAs/SM.
// ---------------------------------------------------------------------------
__global__ __launch_bounds__(256, 2) void proj_pv(
    const float* __restrict__ v, const float* __restrict__ Wv)
{
    extern __shared__ float sm[];
    float (*As)[32][132] = (float(*)[32][132])sm;
    float (*Bs)[128][36] = (float(*)[128][36])(sm + 2 * 32 * 132);

    const int t = threadIdx.x;
    const int warp = t >> 5;
    const int wm = warp >> 2;
    const int wn = warp & 3;
    const int nt = blockIdx.x;
    const int mg0 = blockIdx.y * 128;
    const int b = mg0 >> 12;
    const int pix0 = mg0 & 4095;
    const float* xb = v + (size_t)b * CC * HW + pix0;
    const float* Wb = Wv + (size_t)(nt * 128) * CC;

    wmma::fragment<wmma::accumulator, 16, 16, 8, float> acc[4][2];
#pragma unroll
    for (int i = 0; i < 4; i++)
#pragma unroll
        for (int j = 0; j < 2; j++) wmma::fill_fragment(acc[i][j], 0.0f);

    auto stage = [&](int buf, int c0) {
#pragma unroll
        for (int i = 0; i < 4; i++) {
            int idx = t + i * 256;
            int r = idx >> 5, c4 = idx & 31;
            cpa16(sptr(&As[buf][r][c4 * 4]), xb + (size_t)(c0 + r) * HW + c4 * 4);
        }
#pragma unroll
        for (int i = 0; i < 4; i++) {
            int idx = t + i * 256;
            int n = idx >> 3, k4 = idx & 7;
            cpa16(sptr(&Bs[buf][n][k4 * 4]), Wb + (size_t)n * CC + c0 + k4 * 4);
        }
        CP_COMMIT();
    };

    stage(0, 0);
    for (int kc = 0; kc < 16; kc++) {
        const int cur = kc & 1;
        if (kc < 15) { stage(cur ^ 1, (kc + 1) * 32); CP_WAIT(1); }
        else         { CP_WAIT(0); }
        __syncthreads();
#pragma unroll
        for (int ks = 0; ks < 4; ks++) {
            wmma::fragment<wmma::matrix_a, 16, 16, 8, wmma::precision::tf32,
                           wmma::col_major> a[4];
#pragma unroll
            for (int i = 0; i < 4; i++)
                wmma::load_matrix_sync(a[i], &As[cur][ks * 8][wm * 64 + i * 16], 132);
            wmma::fragment<wmma::matrix_b, 16, 16, 8, wmma::precision::tf32,
                           wmma::col_major> bf[2];
#pragma unroll
            for (int j = 0; j < 2; j++)
                wmma::load_matrix_sync(bf[j], &Bs[cur][wn * 32 + j * 16][ks * 8], 36);
#pragma unroll
            for (int i = 0; i < 4; i++)
#pragma unroll
                for (int j = 0; j < 2; j++)
                    wmma::mma_sync(acc[i][j], a[i], bf[j], acc[i][j]);
        }
        __syncthreads();
    }
#pragma unroll
    for (int i = 0; i < 4; i++)
#pragma unroll
        for (int j = 0; j < 2; j++)
            wmma::store_matrix_sync(
                g_pv + (size_t)(mg0 + wm * 64 + i * 16) * CC
                     + nt * 128 + wn * 32 + j * 16,
                acc[i][j], CC, wmma::mem_row_major);
}

// ---------------------------------------------------------------------------
// Attention scores, fp32 FFMA (bias added during staging). 512 threads.
// blockIdx.z = mode. mode 0: per (b,w) S[h][g] + diag mask; mode 1: per (b,h).
// ---------------------------------------------------------------------------
__global__ __launch_bounds__(512) void scores_kernel(
    const float* __restrict__ bq, const float* __restrict__ bk)
{
    __shared__ float As[64][65];
    __shared__ float Bs[64][65];
    const int t = threadIdx.x;
    const int q = blockIdx.x;
    const int b = blockIdx.y;
    const int mode = blockIdx.z;

    size_t base; int rs;
    if (mode == 0) { base = ((size_t)b * HW + q) * 64;      rs = 4096; }
    else           { base = ((size_t)b * HW + q * 64) * 64; rs = 64;   }

    for (int idx = t; idx < 4096; idx += 512) {
        int i = idx >> 6, c = idx & 63;
        As[i][c] = g_pq[base + (size_t)i * rs + c] + bq[c];
        Bs[i][c] = g_pk[base + (size_t)i * rs + c] + bk[c];
    }
    __syncthreads();

    const int i0 = (t & 15) * 4;
    const int j0 = (t >> 4) * 2;
    float acc[4][2];
#pragma unroll
    for (int ii = 0; ii < 4; ii++) { acc[ii][0] = 0.f; acc[ii][1] = 0.f; }

#pragma unroll 8
    for (int c = 0; c < 64; c++) {
        float a0 = As[i0 + 0][c], a1 = As[i0 + 1][c];
        float a2 = As[i0 + 2][c], a3 = As[i0 + 3][c];
        float b0 = Bs[j0 + 0][c], b1 = Bs[j0 + 1][c];
        acc[0][0] += a0 * b0; acc[0][1] += a0 * b1;
        acc[1][0] += a1 * b0; acc[1][1] += a1 * b1;
        acc[2][0] += a2 * b0; acc[2][1] += a2 * b1;
        acc[3][0] += a3 * b0; acc[3][1] += a3 * b1;
    }

#pragma unroll
    for (int ii = 0; ii < 4; ii++) {
#pragma unroll
        for (int jj = 0; jj < 2; jj++) {
            int i = i0 + ii, j = j0 + jj;
            float v = acc[ii][jj];
            size_t o;
            if (mode == 0) {
                if (i == j) v = -1e30f;
                o = (((size_t)b * HH + i) * WW + q) * 128 + j;
            } else {
                o = (((size_t)b * HH + q) * WW + i) * 128 + 64 + j;
            }
            g_att[o] = v;
        }
    }
}

// ---------------------------------------------------------------------------
// Softmax over 128 concatenated logits; one warp per row.
// ---------------------------------------------------------------------------
__global__ __launch_bounds__(256) void softmax_kernel()
{
    const int r    = (blockIdx.x * 256 + threadIdx.x) >> 5;
    const int lane = threadIdx.x & 31;
    float4* row = (float4*)(g_att + (size_t)r * 128);
    float4 v = row[lane];
    float m = fmaxf(fmaxf(v.x, v.y), fmaxf(v.z, v.w));
#pragma unroll
    for (int o = 16; o > 0; o >>= 1) m = fmaxf(m, __shfl_xor_sync(0xffffffffu, m, o));
    v.x = __expf(v.x - m); v.y = __expf(v.y - m);
    v.z = __expf(v.z - m); v.w = __expf(v.w - m);
    float s = v.x + v.y + v.z + v.w;
#pragma unroll
    for (int o = 16; o > 0; o >>= 1) s += __shfl_xor_sync(0xffffffffu, s, o);
    float inv = 1.0f / s;
    v.x *= inv; v.y *= inv; v.z *= inv; v.w *= inv;
    row[lane] = v;
}

// ---------------------------------------------------------------------------
// tmpH[b,w,h,c] = sum_g attH[b,h,w,g] * pv[b,pix(g,w),c]
// cp.async pipeline over 4 c-chunks. 8 warps = 4(h:16) x 2(c:64). 2 CTAs/SM.
// ---------------------------------------------------------------------------
__global__ __launch_bounds__(256, 2) void tmph_wmma()
{
    extern __shared__ float sm[];
    float (*Att)[68] = (float(*)[68])sm;                       // [h][g]
    float (*Ps)[64][132] = (float(*)[64][132])(sm + 64 * 68);  // [buf][g][c]
    const int t = threadIdx.x, w = blockIdx.x, b = blockIdx.y;
    const int warp = t >> 5;
    const int wh = warp >> 1;
    const int wc = warp & 1;

    auto stage = [&](int buf, int c0) {
#pragma unroll
        for (int i = 0; i < 8; i++) {
            int idx = t + i * 256;
            int g = idx >> 5, c4 = idx & 31;
            cpa16(sptr(&Ps[buf][g][c4 * 4]),
                  g_pv + ((size_t)b * HW + g * WW + w) * CC + c0 + c4 * 4);
        }
        CP_COMMIT();
    };

    stage(0, 0);
#pragma unroll
    for (int i = 0; i < 4; i++) {
        int idx = t + i * 256;
        int h = idx >> 4, g4 = idx & 15;
        ((float4*)&Att[h][0])[g4] =
            *(const float4*)(g_att + (((size_t)b * HH + h) * WW + w) * 128 + g4 * 4);
    }

    for (int kc = 0; kc < 4; kc++) {
        const int cur = kc & 1;
        const int c0 = kc * 128;
        if (kc < 3) { stage(cur ^ 1, c0 + 128); CP_WAIT(1); }
        else        { CP_WAIT(0); }
        __syncthreads();

        wmma::fragment<wmma::accumulator, 16, 16, 8, float> acc[4];
#pragma unroll
        for (int i = 0; i < 4; i++) wmma::fill_fragment(acc[i], 0.0f);
#pragma unroll
        for (int ks = 0; ks < 8; ks++) {
            wmma::fragment<wmma::matrix_a, 16, 16, 8, wmma::precision::tf32,
                           wmma::row_major> a;
            wmma::load_matrix_sync(a, &Att[wh * 16][ks * 8], 68);
#pragma unroll
            for (int ci = 0; ci < 4; ci++) {
                wmma::fragment<wmma::matrix_b, 16, 16, 8, wmma::precision::tf32,
                               wmma::row_major> bf;
                wmma::load_matrix_sync(bf, &Ps[cur][ks * 8][wc * 64 + ci * 16], 132);
                wmma::mma_sync(acc[ci], a, bf, acc[ci]);
            }
        }
        float* dst = g_tmpH + (((size_t)b * WW + w) * HH + wh * 16) * CC + c0;
#pragma unroll
        for (int ci = 0; ci < 4; ci++)
            wmma::store_matrix_sync(dst + wc * 64 + ci * 16, acc[ci], CC,
                                    wmma::mem_row_major);
        __syncthreads();
    }
}

// ---------------------------------------------------------------------------
// Final per (b,h): Sw[w][c] = sum_f attW[b,h,w,f] * pv[b,pix(h,f),c];
// out[b,c,h,w] = value + gamma * (Sw + tmpH[b,w,h,c] + bv[c])
// ---------------------------------------------------------------------------
__global__ __launch_bounds__(256) void final_wmma(
    const float* __restrict__ value, const float* __restrict__ bv,
    const float* __restrict__ gamma, float* __restrict__ out)
{
    extern __shared__ float sm[];
    float (*Att)[68] = (float(*)[68])sm;                        // [w][f]
    float (*Ps)[64][132] = (float(*)[64][132])(sm + 64 * 68);   // [buf][f][c]
    float (*Osm)[132] = (float(*)[132])(sm + 64 * 68 + 2 * 64 * 132); // [w][c0..c127]
    const int t = threadIdx.x, h = blockIdx.x, b = blockIdx.y;
    const int warp = t >> 5;
    const int ww = warp >> 1;
    const int wc = warp & 1;
    const float gm = gamma[0];

    auto stage = [&](int buf, int c0) {
#pragma unroll
        for (int i = 0; i < 8; i++) {
            int idx = t + i * 256;
            int f = idx >> 5, c4 = idx & 31;
            cpa16(sptr(&Ps[buf][f][c4 * 4]),
                  g_pv + ((size_t)b * HW + h * WW + f) * CC + c0 + c4 * 4);
        }
        CP_COMMIT();
    };

    stage(0, 0);
#pragma unroll
    for (int i = 0; i < 4; i++) {
        int idx = t + i * 256;
        int w = idx >> 4, f4 = idx & 15;
        ((float4*)&Att[w][0])[f4] = *(const float4*)(
            g_att + (((size_t)b * HH + h) * WW + w) * 128 + 64 + f4 * 4);
    }

    const int w4 = t & 15;
    const int cB = t >> 4;

    for (int kc = 0; kc < 4; kc++) {
        const int cur = kc & 1;
        const int c0 = kc * 128;
        if (kc < 3) { stage(cur ^ 1, c0 + 128); CP_WAIT(1); }
        else        { CP_WAIT(0); }
        __syncthreads();

        wmma::fragment<wmma::accumulator, 16, 16, 8, float> acc[4];
#pragma unroll
        for (int i = 0; i < 4; i++) wmma::fill_fragment(acc[i], 0.0f);
#pragma unroll
        for (int ks = 0; ks < 8; ks++) {
            wmma::fragment<wmma::matrix_a, 16, 16, 8, wmma::precision::tf32,
                           wmma::row_major> a;
            wmma::load_matrix_sync(a, &Att[ww * 16][ks * 8], 68);
#pragma unroll
            for (int ci = 0; ci < 4; ci++) {
                wmma::fragment<wmma::matrix_b, 16, 16, 8, wmma::precision::tf32,
                               wmma::row_major> bf;
                wmma::load_matrix_sync(bf, &Ps[cur][ks * 8][wc * 64 + ci * 16], 132);
                wmma::mma_sync(acc[ci], a, bf, acc[ci]);
            }
        }
#pragma unroll
        for (int ci = 0; ci < 4; ci++)
            wmma::store_matrix_sync(&Osm[ww * 16][wc * 64 + ci * 16], acc[ci], 132,
                                    wmma::mem_row_major);
        __syncthreads();

        float th[4][8];
#pragma unroll
        for (int wi = 0; wi < 4; wi++) {
            const float* tp = g_tmpH +
                (((size_t)b * WW + w4 * 4 + wi) * HH + h) * CC + c0 + cB * 8;
            float4 u0 = *(const float4*)tp;
            float4 u1 = *(const float4*)(tp + 4);
            th[wi][0] = u0.x; th[wi][1] = u0.y; th[wi][2] = u0.z; th[wi][3] = u0.w;
            th[wi][4] = u1.x; th[wi][5] = u1.y; th[wi][6] = u1.z; th[wi][7] = u1.w;
        }
#pragma unroll
        for (int ci = 0; ci < 8; ci++) {
            int c = c0 + cB * 8 + ci;
            float bvv = bv[c];
            size_t vbase = (((size_t)b * CC + c) * HH + h) * WW;
            float4 vv = ((const float4*)(value + vbase))[w4];
            float4 ov;
            ov.x = vv.x + gm * (Osm[w4 * 4 + 0][cB * 8 + ci] + th[0][ci] + bvv);
            ov.y = vv.y + gm * (Osm[w4 * 4 + 1][cB * 8 + ci] + th[1][ci] + bvv);
            ov.z = vv.z + gm * (Osm[w4 * 4 + 2][cB * 8 + ci] + th[2][ci] + bvv);
            ov.w = vv.w + gm * (Osm[w4 * 4 + 3][cB * 8 + ci] + th[3][ci] + bvv);
            ((float4*)(out + vbase))[w4] = ov;
        }
        __syncthreads();
    }
}

// ---------------------------------------------------------------------------
#define SMEM_QK  ((2 * 32 * 132 + 2 * 64 * 36) * 4)                  // 52224
#define SMEM_PV  ((2 * 32 * 132 + 2 * 128 * 36) * 4)                 // 70656
#define SMEM_TH  ((64 * 68 + 2 * 64 * 132) * 4)                      // 84992
#define SMEM_FN  ((64 * 68 + 2 * 64 * 132 + 64 * 132) * 4)           // 118784

extern "C" void kernel_launch(void* const* d_in, const int* in_sizes, int n_in,
                              void* d_out, int out_size)
{
    (void)in_sizes; (void)n_in; (void)out_size;
    const float* query = (const float*)d_in[0];
    const float* key_t = (const float*)d_in[1];
    const float* value = (const float*)d_in[2];
    const float* Wq    = (const float*)d_in[3];
    const float* bq    = (const float*)d_in[4];
    const float* Wk    = (const float*)d_in[5];
    const float* bk    = (const float*)d_in[6];
    const float* Wv    = (const float*)d_in[7];
    const float* bv    = (const float*)d_in[8];
    const float* gamma = (const float*)d_in[9];
    float* out = (float*)d_out;

    cudaFuncSetAttribute(proj_qk,    cudaFuncAttributeMaxDynamicSharedMemorySize, SMEM_QK);
    cudaFuncSetAttribute(proj_pv,    cudaFuncAttributeMaxDynamicSharedMemorySize, SMEM_PV);
    cudaFuncSetAttribute(tmph_wmma,  cudaFuncAttributeMaxDynamicSharedMemorySize, SMEM_TH);
    cudaFuncSetAttribute(final_wmma, cudaFuncAttributeMaxDynamicSharedMemorySize, SMEM_FN);

    // Order chosen so the 4th launch (= the one ncu captures) is proj_pv.
    // Dependencies: scores needs pq/pk only; proj_pv needs value only.
    proj_qk<<<dim3(256, 2), 256, SMEM_QK>>>(query, Wq, key_t, Wk);   // 1
    scores_kernel<<<dim3(64, BB, 2), 512>>>(bq, bk);                 // 2
    softmax_kernel<<<4096, 256>>>();                                 // 3
    proj_pv<<<dim3(4, 256), 256, SMEM_PV>>>(value, Wv);              // 4 <- profiled
    tmph_wmma<<<dim3(WW, BB), 256, SMEM_TH>>>();                     // 5
    final_wmma<<<dim3(HH, BB), 256, SMEM_FN>>>(value, bv, gamma, out); // 6
}

// round 15
// speedup vs baseline: 2.7343x; 1.8214x over previous
#include <cuda_runtime.h>
#include <cstdint>
#include <cuda_fp16.h>
#include <mma.h>
#include <math.h>

using namespace nvcuda;

#define BB 8
#define CC 512
#define HH 64
#define WW 64
#define HW 4096            // HH*WW

// Scratch (allocation-free: __device__ globals). Projections stored WITHOUT bias.
__device__ float  g_pq[BB * HW * 64];               // [b, pix, o]
__device__ float  g_pk[BB * HW * 64];               // [b, pix, o]
__device__ __half g_pvh[(size_t)BB * HW * CC];      // [b, pix, c]  fp16
__device__ float  g_att[(size_t)BB * HW * 128];     // [b,h,w, 0:64=attH | 64:128=attW]
__device__ float  g_tmpH[(size_t)BB * HW * CC];     // [b, w, h, c]
__device__ __half g_vh[(size_t)BB * CC * HW];       // v in fp16, [b, c, pix]
__device__ __half g_Wvh[512 * 512];                 // Wv in fp16, [n, k]

// ---- cp.async helpers -----------------------------------------------------
__device__ __forceinline__ unsigned sptr(const void* p) {
    return (unsigned)__cvta_generic_to_shared(p);
}
__device__ __forceinline__ void cpa16(unsigned s, const void* g) {
    asm volatile("cp.async.cg.shared.global [%0], [%1], 16;\n" :: "r"(s), "l"(g));
}
#define CP_COMMIT() asm volatile("cp.async.commit_group;\n" ::: "memory")
#define CP_WAIT(n)  asm volatile("cp.async.wait_group %0;\n" :: "n"(n) : "memory")

// ---------------------------------------------------------------------------
// fp32 -> fp16 streaming converts
// ---------------------------------------------------------------------------
__global__ __launch_bounds__(256) void prep_v(const float* __restrict__ v)
{
    size_t i = ((size_t)blockIdx.x * 256 + threadIdx.x) * 4;
    float4 f = *(const float4*)(v + i);
    __half2 h0 = __floats2half2_rn(f.x, f.y);
    __half2 h1 = __floats2half2_rn(f.z, f.w);
    *(uint2*)(g_vh + i) = make_uint2(*(unsigned*)&h0, *(unsigned*)&h1);
}
__global__ __launch_bounds__(256) void prep_w(const float* __restrict__ Wv)
{
    size_t i = ((size_t)blockIdx.x * 256 + threadIdx.x) * 4;
    float4 f = *(const float4*)(Wv + i);
    __half2 h0 = __floats2half2_rn(f.x, f.y);
    __half2 h1 = __floats2half2_rn(f.z, f.w);
    *(uint2*)(g_Wvh + i) = make_uint2(*(unsigned*)&h0, *(unsigned*)&h1);
}

// ---------------------------------------------------------------------------
// q/k projection (tf32, unchanged — DRAM-bound): out[b,pix,o] = sum_c W[o,c]*x[b,c,pix]
// ---------------------------------------------------------------------------
__global__ __launch_bounds__(256, 2) void proj_qk(
    const float* __restrict__ q, const float* __restrict__ Wq,
    const float* __restrict__ kk, const float* __restrict__ Wk)
{
    extern __shared__ float sm[];
    float (*As)[32][132] = (float(*)[32][132])sm;
    float (*Bs)[64][36]  = (float(*)[64][36])(sm + 2 * 32 * 132);

    const int t = threadIdx.x;
    const int warp = t >> 5;
    const int wm = warp >> 1;
    const int wn = warp & 1;
    const int mg0 = blockIdx.x * 128;
    const int b = mg0 >> 12;
    const int pix0 = mg0 & 4095;

    const float* x = blockIdx.y ? kk : q;
    const float* W = blockIdx.y ? Wk : Wq;
    float* outp    = blockIdx.y ? g_pk : g_pq;
    const float* xb = x + (size_t)b * CC * HW + pix0;

    wmma::fragment<wmma::accumulator, 16, 16, 8, float> acc[2][2];
#pragma unroll
    for (int i = 0; i < 2; i++)
#pragma unroll
        for (int j = 0; j < 2; j++) wmma::fill_fragment(acc[i][j], 0.0f);

    auto stage = [&](int buf, int c0) {
#pragma unroll
        for (int i = 0; i < 4; i++) {
            int idx = t + i * 256;
            int r = idx >> 5, c4 = idx & 31;
            cpa16(sptr(&As[buf][r][c4 * 4]), xb + (size_t)(c0 + r) * HW + c4 * 4);
        }
#pragma unroll
        for (int i = 0; i < 2; i++) {
            int idx = t + i * 256;
            int n = idx >> 3, k4 = idx & 7;
            cpa16(sptr(&Bs[buf][n][k4 * 4]), W + (size_t)n * CC + c0 + k4 * 4);
        }
        CP_COMMIT();
    };

    stage(0, 0);
    for (int kc = 0; kc < 16; kc++) {
        const int cur = kc & 1;
        if (kc < 15) { stage(cur ^ 1, (kc + 1) * 32); CP_WAIT(1); }
        else         { CP_WAIT(0); }
        __syncthreads();
#pragma unroll
        for (int ks = 0; ks < 4; ks++) {
            wmma::fragment<wmma::matrix_a, 16, 16, 8, wmma::precision::tf32,
                           wmma::col_major> a[2];
            wmma::load_matrix_sync(a[0], &As[cur][ks * 8][wm * 32], 132);
            wmma::load_matrix_sync(a[1], &As[cur][ks * 8][wm * 32 + 16], 132);
            wmma::fragment<wmma::matrix_b, 16, 16, 8, wmma::precision::tf32,
                           wmma::col_major> bf[2];
            wmma::load_matrix_sync(bf[0], &Bs[cur][wn * 32][ks * 8], 36);
            wmma::load_matrix_sync(bf[1], &Bs[cur][wn * 32 + 16][ks * 8], 36);
#pragma unroll
            for (int i = 0; i < 2; i++)
#pragma unroll
                for (int j = 0; j < 2; j++)
                    wmma::mma_sync(acc[i][j], a[i], bf[j], acc[i][j]);
        }
        __syncthreads();
    }
#pragma unroll
    for (int i = 0; i < 2; i++)
#pragma unroll
        for (int j = 0; j < 2; j++)
            wmma::store_matrix_sync(
                outp + (size_t)(mg0 + wm * 32 + i * 16) * 64 + wn * 32 + j * 16,
                acc[i][j], 64, wmma::mem_row_major);
}

// ---------------------------------------------------------------------------
// v projection, fp16 HMMA: pvh[b,pix,n] = sum_c v[b,c,pix]*Wv[n,c]  (no bias)
// 128 pixels x 128 c per CTA; 8 warps = 2(m:64) x 4(n:32), acc 4x2 fp32 frags.
// K = 512 in 8 chunks of 64, 2-stage cp.async, fp16 operands, fp16 output.
// ---------------------------------------------------------------------------
__global__ __launch_bounds__(256, 2) void proj_pv()
{
    extern __shared__ float smf[];
    __half (*As)[64][136] = (__half(*)[64][136])smf;                 // [buf][k][m]
    __half (*Bs)[128][72] = (__half(*)[128][72])((char*)smf + 2 * 64 * 136 * 2);
    float  (*Osm)[132]    = (float(*)[132])smf;                      // epilogue reuse

    const int t = threadIdx.x;
    const int warp = t >> 5;
    const int wm = warp >> 2;       // 0..1 -> m0 = wm*64
    const int wn = warp & 3;        // 0..3 -> n0 = wn*32
    const int nt = blockIdx.x;
    const int mg0 = blockIdx.y * 128;
    const int b = mg0 >> 12;
    const int pix0 = mg0 & 4095;

    const __half* xb = g_vh + (size_t)b * CC * HW + pix0;
    const __half* Wb = g_Wvh + (size_t)(nt * 128) * 512;

    wmma::fragment<wmma::accumulator, 16, 16, 16, float> acc[4][2];
#pragma unroll
    for (int i = 0; i < 4; i++)
#pragma unroll
        for (int j = 0; j < 2; j++) wmma::fill_fragment(acc[i][j], 0.0f);

    auto stage = [&](int buf, int c0) {
#pragma unroll
        for (int i = 0; i < 4; i++) {         // A: 64 rows x 16 x 16B
            int idx = t + i * 256;
            int r = idx >> 4, s = idx & 15;
            cpa16(sptr(&As[buf][r][s * 8]), xb + (size_t)(c0 + r) * HW + s * 8);
        }
#pragma unroll
        for (int i = 0; i < 4; i++) {         // B: 128 rows x 8 x 16B
            int idx = t + i * 256;
            int n = idx >> 3, s = idx & 7;
            cpa16(sptr(&Bs[buf][n][s * 8]), Wb + (size_t)n * 512 + c0 + s * 8);
        }
        CP_COMMIT();
    };

    stage(0, 0);
    for (int kc = 0; kc < 8; kc++) {
        const int cur = kc & 1;
        if (kc < 7) { stage(cur ^ 1, (kc + 1) * 64); CP_WAIT(1); }
        else        { CP_WAIT(0); }
        __syncthreads();
#pragma unroll
        for (int ks = 0; ks < 4; ks++) {
            wmma::fragment<wmma::matrix_a, 16, 16, 16, __half,
                           wmma::col_major> a[4];
#pragma unroll
            for (int i = 0; i < 4; i++)
                wmma::load_matrix_sync(a[i], &As[cur][ks * 16][wm * 64 + i * 16], 136);
            wmma::fragment<wmma::matrix_b, 16, 16, 16, __half,
                           wmma::col_major> bf[2];
#pragma unroll
            for (int j = 0; j < 2; j++)
                wmma::load_matrix_sync(bf[j], &Bs[cur][wn * 32 + j * 16][ks * 16], 72);
#pragma unroll
            for (int i = 0; i < 4; i++)
#pragma unroll
                for (int j = 0; j < 2; j++)
                    wmma::mma_sync(acc[i][j], a[i], bf[j], acc[i][j]);
        }
        __syncthreads();
    }

    // Epilogue: stage fp32 result [128 pix][128 c] in smem, convert to fp16.
#pragma unroll
    for (int i = 0; i < 4; i++)
#pragma unroll
        for (int j = 0; j < 2; j++)
            wmma::store_matrix_sync(&Osm[wm * 64 + i * 16][wn * 32 + j * 16],
                                    acc[i][j], 132, wmma::mem_row_major);
    __syncthreads();
#pragma unroll
    for (int i = 0; i < 16; i++) {
        int idx = t + i * 256;                 // 4096 float4
        int row = idx >> 5, c4 = idx & 31;
        float4 f = *(float4*)&Osm[row][c4 * 4];
        __half2 h0 = __floats2half2_rn(f.x, f.y);
        __half2 h1 = __floats2half2_rn(f.z, f.w);
        *(uint2*)(g_pvh + (size_t)(mg0 + row) * CC + nt * 128 + c4 * 4) =
            make_uint2(*(unsigned*)&h0, *(unsigned*)&h1);
    }
}

// ---------------------------------------------------------------------------
// Attention scores, fp32 FFMA (bias added during staging). 512 threads.
// ---------------------------------------------------------------------------
__global__ __launch_bounds__(512) void scores_kernel(
    const float* __restrict__ bq, const float* __restrict__ bk)
{
    __shared__ float As[64][65];
    __shared__ float Bs[64][65];
    const int t = threadIdx.x;
    const int q = blockIdx.x;
    const int b = blockIdx.y;
    const int mode = blockIdx.z;

    size_t base; int rs;
    if (mode == 0) { base = ((size_t)b * HW + q) * 64;      rs = 4096; }
    else           { base = ((size_t)b * HW + q * 64) * 64; rs = 64;   }

    for (int idx = t; idx < 4096; idx += 512) {
        int i = idx >> 6, c = idx & 63;
        As[i][c] = g_pq[base + (size_t)i * rs + c] + bq[c];
        Bs[i][c] = g_pk[base + (size_t)i * rs + c] + bk[c];
    }
    __syncthreads();

    const int i0 = (t & 15) * 4;
    const int j0 = (t >> 4) * 2;
    float acc[4][2];
#pragma unroll
    for (int ii = 0; ii < 4; ii++) { acc[ii][0] = 0.f; acc[ii][1] = 0.f; }

#pragma unroll 8
    for (int c = 0; c < 64; c++) {
        float a0 = As[i0 + 0][c], a1 = As[i0 + 1][c];
        float a2 = As[i0 + 2][c], a3 = As[i0 + 3][c];
        float b0 = Bs[j0 + 0][c], b1 = Bs[j0 + 1][c];
        acc[0][0] += a0 * b0; acc[0][1] += a0 * b1;
        acc[1][0] += a1 * b0; acc[1][1] += a1 * b1;
        acc[2][0] += a2 * b0; acc[2][1] += a2 * b1;
        acc[3][0] += a3 * b0; acc[3][1] += a3 * b1;
    }

#pragma unroll
    for (int ii = 0; ii < 4; ii++) {
#pragma unroll
        for (int jj = 0; jj < 2; jj++) {
            int i = i0 + ii, j = j0 + jj;
            float v = acc[ii][jj];
            size_t o;
            if (mode == 0) {
                if (i == j) v = -1e30f;
                o = (((size_t)b * HH + i) * WW + q) * 128 + j;
            } else {
                o = (((size_t)b * HH + q) * WW + i) * 128 + 64 + j;
            }
            g_att[o] = v;
        }
    }
}

// ---------------------------------------------------------------------------
// Softmax over 128 concatenated logits; one warp per row.
// ---------------------------------------------------------------------------
__global__ __launch_bounds__(256) void softmax_kernel()
{
    const int r    = (blockIdx.x * 256 + threadIdx.x) >> 5;
    const int lane = threadIdx.x & 31;
    float4* row = (float4*)(g_att + (size_t)r * 128);
    float4 v = row[lane];
    float m = fmaxf(fmaxf(v.x, v.y), fmaxf(v.z, v.w));
#pragma unroll
    for (int o = 16; o > 0; o >>= 1) m = fmaxf(m, __shfl_xor_sync(0xffffffffu, m, o));
    v.x = __expf(v.x - m); v.y = __expf(v.y - m);
    v.z = __expf(v.z - m); v.w = __expf(v.w - m);
    float s = v.x + v.y + v.z + v.w;
#pragma unroll
    for (int o = 16; o > 0; o >>= 1) s += __shfl_xor_sync(0xffffffffu, s, o);
    float inv = 1.0f / s;
    v.x *= inv; v.y *= inv; v.z *= inv; v.w *= inv;
    row[lane] = v;
}

// ---------------------------------------------------------------------------
// tmpH[b,w,h,c] = sum_g attH[b,h,w,g] * pvh[b,pix(g,w),c]   (fp16 MMA)
// 8 warps = 4(h:16) x 2(c:64); cp.async pipeline over 4 c-chunks of 128.
// ---------------------------------------------------------------------------
__global__ __launch_bounds__(256, 2) void tmph_h()
{
    extern __shared__ float smf[];
    __half (*Att)[72]     = (__half(*)[72])smf;                       // [h][g]
    __half (*Ps)[64][136] = (__half(*)[64][136])((char*)smf + 64 * 72 * 2);
    const int t = threadIdx.x, w = blockIdx.x, b = blockIdx.y;
    const int warp = t >> 5;
    const int wh = warp >> 1;
    const int wc = warp & 1;

    auto stage = [&](int buf, int c0) {
#pragma unroll
        for (int i = 0; i < 4; i++) {          // 64 rows x 16 x 16B
            int idx = t + i * 256;
            int g = idx >> 4, s = idx & 15;
            cpa16(sptr(&Ps[buf][g][s * 8]),
                  g_pvh + ((size_t)b * HW + g * WW + w) * CC + c0 + s * 8);
        }
        CP_COMMIT();
    };

    stage(0, 0);
#pragma unroll
    for (int i = 0; i < 4; i++) {              // Att: 1024 float4 -> half
        int idx = t + i * 256;
        int h = idx >> 4, g4 = idx & 15;
        float4 f = *(const float4*)(g_att + (((size_t)b * HH + h) * WW + w) * 128 + g4 * 4);
        __half2 h0 = __floats2half2_rn(f.x, f.y);
        __half2 h1 = __floats2half2_rn(f.z, f.w);
        *(uint2*)&Att[h][g4 * 4] = make_uint2(*(unsigned*)&h0, *(unsigned*)&h1);
    }

    for (int kc = 0; kc < 4; kc++) {
        const int cur = kc & 1;
        const int c0 = kc * 128;
        if (kc < 3) { stage(cur ^ 1, c0 + 128); CP_WAIT(1); }
        else        { CP_WAIT(0); }
        __syncthreads();

        wmma::fragment<wmma::accumulator, 16, 16, 16, float> acc[4];
#pragma unroll
        for (int i = 0; i < 4; i++) wmma::fill_fragment(acc[i], 0.0f);
#pragma unroll
        for (int ks = 0; ks < 4; ks++) {
            wmma::fragment<wmma::matrix_a, 16, 16, 16, __half,
                           wmma::row_major> a;
            wmma::load_matrix_sync(a, &Att[wh * 16][ks * 16], 72);
#pragma unroll
            for (int ci = 0; ci < 4; ci++) {
                wmma::fragment<wmma::matrix_b, 16, 16, 16, __half,
                               wmma::row_major> bf;
                wmma::load_matrix_sync(bf, &Ps[cur][ks * 16][wc * 64 + ci * 16], 136);
                wmma::mma_sync(acc[ci], a, bf, acc[ci]);
            }
        }
        float* dst = g_tmpH + (((size_t)b * WW + w) * HH + wh * 16) * CC + c0;
#pragma unroll
        for (int ci = 0; ci < 4; ci++)
            wmma::store_matrix_sync(dst + wc * 64 + ci * 16, acc[ci], CC,
                                    wmma::mem_row_major);
        __syncthreads();
    }
}

// ---------------------------------------------------------------------------
// Final per (b,h): Sw[w][c] = sum_f attW[b,h,w,f] * pvh[b,pix(h,f),c] (fp16 MMA)
// out[b,c,h,w] = value + gamma * (Sw + tmpH[b,w,h,c] + bv[c])
// ---------------------------------------------------------------------------
__global__ __launch_bounds__(256, 2) void final_h(
    const float* __restrict__ value, const float* __restrict__ bv,
    const float* __restrict__ gamma, float* __restrict__ out)
{
    extern __shared__ float smf[];
    __half (*Att)[72]     = (__half(*)[72])smf;                        // [w][f]
    __half (*Ps)[64][136] = (__half(*)[64][136])((char*)smf + 64 * 72 * 2);
    float  (*Osm)[132]    = (float(*)[132])((char*)smf + 64 * 72 * 2 + 2 * 64 * 136 * 2);
    const int t = threadIdx.x, h = blockIdx.x, b = blockIdx.y;
    const int warp = t >> 5;
    const int ww = warp >> 1;
    const int wc = warp & 1;
    const float gm = gamma[0];

    auto stage = [&](int buf, int c0) {
#pragma unroll
        for (int i = 0; i < 4; i++) {
            int idx = t + i * 256;
            int f = idx >> 4, s = idx & 15;
            cpa16(sptr(&Ps[buf][f][s * 8]),
                  g_pvh + ((size_t)b * HW + h * WW + f) * CC + c0 + s * 8);
        }
        CP_COMMIT();
    };

    stage(0, 0);
#pragma unroll
    for (int i = 0; i < 4; i++) {
        int idx = t + i * 256;
        int w = idx >> 4, f4 = idx & 15;
        float4 f = *(const float4*)(
            g_att + (((size_t)b * HH + h) * WW + w) * 128 + 64 + f4 * 4);
        __half2 h0 = __floats2half2_rn(f.x, f.y);
        __half2 h1 = __floats2half2_rn(f.z, f.w);
        *(uint2*)&Att[w][f4 * 4] = make_uint2(*(unsigned*)&h0, *(unsigned*)&h1);
    }

    const int w4 = t & 15;          // epilogue: 4 consecutive w
    const int cB = t >> 4;          // epilogue: 8 consecutive c

    for (int kc = 0; kc < 4; kc++) {
        const int cur = kc & 1;
        const int c0 = kc * 128;
        if (kc < 3) { stage(cur ^ 1, c0 + 128); CP_WAIT(1); }
        else        { CP_WAIT(0); }
        __syncthreads();

        wmma::fragment<wmma::accumulator, 16, 16, 16, float> acc[4];
#pragma unroll
        for (int i = 0; i < 4; i++) wmma::fill_fragment(acc[i], 0.0f);
#pragma unroll
        for (int ks = 0; ks < 4; ks++) {
            wmma::fragment<wmma::matrix_a, 16, 16, 16, __half,
                           wmma::row_major> a;
            wmma::load_matrix_sync(a, &Att[ww * 16][ks * 16], 72);
#pragma unroll
            for (int ci = 0; ci < 4; ci++) {
                wmma::fragment<wmma::matrix_b, 16, 16, 16, __half,
                               wmma::row_major> bf;
                wmma::load_matrix_sync(bf, &Ps[cur][ks * 16][wc * 64 + ci * 16], 136);
                wmma::mma_sync(acc[ci], a, bf, acc[ci]);
            }
        }
#pragma unroll
        for (int ci = 0; ci < 4; ci++)
            wmma::store_matrix_sync(&Osm[ww * 16][wc * 64 + ci * 16], acc[ci], 132,
                                    wmma::mem_row_major);
        __syncthreads();

        float th[4][8];
#pragma unroll
        for (int wi = 0; wi < 4; wi++) {
            const float* tp = g_tmpH +
                (((size_t)b * WW + w4 * 4 + wi) * HH + h) * CC + c0 + cB * 8;
            float4 u0 = *(const float4*)tp;
            float4 u1 = *(const float4*)(tp + 4);
            th[wi][0] = u0.x; th[wi][1] = u0.y; th[wi][2] = u0.z; th[wi][3] = u0.w;
            th[wi][4] = u1.x; th[wi][5] = u1.y; th[wi][6] = u1.z; th[wi][7] = u1.w;
        }
#pragma unroll
        for (int ci = 0; ci < 8; ci++) {
            int c = c0 + cB * 8 + ci;
            float bvv = bv[c];
            size_t vbase = (((size_t)b * CC + c) * HH + h) * WW;
            float4 vv = ((const float4*)(value + vbase))[w4];
            float4 ov;
            ov.x = vv.x + gm * (Osm[w4 * 4 + 0][cB * 8 + ci] + th[0][ci] + bvv);
            ov.y = vv.y + gm * (Osm[w4 * 4 + 1][cB * 8 + ci] + th[1][ci] + bvv);
            ov.z = vv.z + gm * (Osm[w4 * 4 + 2][cB * 8 + ci] + th[2][ci] + bvv);
            ov.w = vv.w + gm * (Osm[w4 * 4 + 3][cB * 8 + ci] + th[3][ci] + bvv);
            ((float4*)(out + vbase))[w4] = ov;
        }
        __syncthreads();
    }
}

// ---------------------------------------------------------------------------
#define SMEM_QK  ((2 * 32 * 132 + 2 * 64 * 36) * 4)                   // 52224
#define SMEM_PV  (2 * 64 * 136 * 2 + 2 * 128 * 72 * 2)                // 71680 (>= Osm 67584)
#define SMEM_TH  (64 * 72 * 2 + 2 * 64 * 136 * 2)                     // 44032
#define SMEM_FN  (64 * 72 * 2 + 2 * 64 * 136 * 2 + 64 * 132 * 4)      // 77824

extern "C" void kernel_launch(void* const* d_in, const int* in_sizes, int n_in,
                              void* d_out, int out_size)
{
    (void)in_sizes; (void)n_in; (void)out_size;
    const float* query = (const float*)d_in[0];
    const float* key_t = (const float*)d_in[1];
    const float* value = (const float*)d_in[2];
    const float* Wq    = (const float*)d_in[3];
    const float* bq    = (const float*)d_in[4];
    const float* Wk    = (const float*)d_in[5];
    const float* bk    = (const float*)d_in[6];
    const float* Wv    = (const float*)d_in[7];
    const float* bv    = (const float*)d_in[8];
    const float* gamma = (const float*)d_in[9];
    float* out = (float*)d_out;

    cudaFuncSetAttribute(proj_qk, cudaFuncAttributeMaxDynamicSharedMemorySize, SMEM_QK);
    cudaFuncSetAttribute(proj_pv, cudaFuncAttributeMaxDynamicSharedMemorySize, SMEM_PV);
    cudaFuncSetAttribute(tmph_h,  cudaFuncAttributeMaxDynamicSharedMemorySize, SMEM_TH);
    cudaFuncSetAttribute(final_h, cudaFuncAttributeMaxDynamicSharedMemorySize, SMEM_FN);

    // Slot 4 (the ncu-captured launch) stays proj_pv.
    prep_v<<<16384, 256>>>(value);                                    // 1
    prep_w<<<256, 256>>>(Wv);                                         // 2
    proj_qk<<<dim3(256, 2), 256, SMEM_QK>>>(query, Wq, key_t, Wk);    // 3
    proj_pv<<<dim3(4, 256), 256, SMEM_PV>>>();                        // 4 <- profiled
    scores_kernel<<<dim3(64, BB, 2), 512>>>(bq, bk);                  // 5
    softmax_kernel<<<4096, 256>>>();                                  // 6
    tmph_h<<<dim3(WW, BB), 256, SMEM_TH>>>();                         // 7
    final_h<<<dim3(HH, BB), 256, SMEM_FN>>>(value, bv, gamma, out);   // 8
}

// round 16
// speedup vs baseline: 4.0066x; 1.4653x over previous
#include <cuda_runtime.h>
#include <cstdint>
#include <cuda_fp16.h>
#include <mma.h>
#include <math.h>

using namespace nvcuda;

#define BB 8
#define CC 512
#define HH 64
#define WW 64
#define HW 4096            // HH*WW

// Scratch (allocation-free: __device__ globals).
__device__ __half g_pqh[BB * HW * 64];              // [b, pix, o]  fp16, bias INCLUDED
__device__ __half g_pkh[BB * HW * 64];              // [b, pix, o]  fp16, bias INCLUDED
__device__ __half g_pvh[(size_t)BB * HW * CC];      // [b, pix, c]  fp16 (no bias)
__device__ float  g_att[(size_t)BB * HW * 128];     // [b,h,w, 0:64=attH | 64:128=attW]
__device__ __half g_tmpHh[(size_t)BB * HW * CC];    // [b, w, h, c] fp16
__device__ __half g_vh[(size_t)BB * CC * HW];       // v in fp16, [b, c, pix]
__device__ __half g_Wvh[512 * 512];                 // Wv in fp16, [n, k]

// ---- cp.async helpers -----------------------------------------------------
__device__ __forceinline__ unsigned sptr(const void* p) {
    return (unsigned)__cvta_generic_to_shared(p);
}
__device__ __forceinline__ void cpa16(unsigned s, const void* g) {
    asm volatile("cp.async.cg.shared.global [%0], [%1], 16;\n" :: "r"(s), "l"(g));
}
#define CP_COMMIT() asm volatile("cp.async.commit_group;\n" ::: "memory")
#define CP_WAIT(n)  asm volatile("cp.async.wait_group %0;\n" :: "n"(n) : "memory")

__device__ __forceinline__ uint2 f4_to_h4(float4 f) {
    __half2 h0 = __floats2half2_rn(f.x, f.y);
    __half2 h1 = __floats2half2_rn(f.z, f.w);
    return make_uint2(*(unsigned*)&h0, *(unsigned*)&h1);
}

// ---------------------------------------------------------------------------
// fp32 -> fp16 streaming converts (v, Wv)
// ---------------------------------------------------------------------------
__global__ __launch_bounds__(256) void prep_v(const float* __restrict__ v)
{
    size_t i = ((size_t)blockIdx.x * 256 + threadIdx.x) * 4;
    *(uint2*)(g_vh + i) = f4_to_h4(*(const float4*)(v + i));
}
__global__ __launch_bounds__(256) void prep_w(const float* __restrict__ Wv)
{
    size_t i = ((size_t)blockIdx.x * 256 + threadIdx.x) * 4;
    *(uint2*)(g_Wvh + i) = f4_to_h4(*(const float4*)(Wv + i));
}

// ---------------------------------------------------------------------------
// q/k projection, fp16 HMMA with on-the-fly fp32->fp16 conversion.
// out_h[b,pix,o] = bias[o] + sum_c W[o,c] * x[b,c,pix]   (fp16, bias included)
// CTA: 128 pix x 64 o; K=512 in 8 chunks of 64. Register-prefetch next chunk.
// 8 warps = 4(m:32) x 2(n:32), acc 2x2 fp32 frags.
// ---------------------------------------------------------------------------
__global__ __launch_bounds__(256, 2) void proj_qk(
    const float* __restrict__ q, const float* __restrict__ Wq,
    const float* __restrict__ kk, const float* __restrict__ Wk,
    const float* __restrict__ bq, const float* __restrict__ bk)
{
    extern __shared__ float smf[];
    __half (*As)[136] = (__half(*)[136])smf;                       // [k=64][m=128]
    __half (*Bs)[72]  = (__half(*)[72])((char*)smf + 64 * 136 * 2);// [n=64][k=64]
    float  (*Osm)[68] = (float(*)[68])smf;                         // [pix=128][o=64] (epilogue reuse)

    const int t = threadIdx.x;
    const int warp = t >> 5;
    const int wm = warp >> 1;
    const int wn = warp & 1;
    const int mg0 = blockIdx.x * 128;
    const int b = mg0 >> 12;
    const int pix0 = mg0 & 4095;

    const float* x    = blockIdx.y ? kk : q;
    const float* W    = blockIdx.y ? Wk : Wq;
    const float* bias = blockIdx.y ? bk : bq;
    __half* outp      = blockIdx.y ? g_pkh : g_pqh;
    const float* xb = x + (size_t)b * CC * HW + pix0;

    wmma::fragment<wmma::accumulator, 16, 16, 16, float> acc[2][2];
#pragma unroll
    for (int i = 0; i < 2; i++)
#pragma unroll
        for (int j = 0; j < 2; j++) wmma::fill_fragment(acc[i][j], 0.0f);

    float4 ra[8], rb[4];
    auto ldreg = [&](int c0) {
#pragma unroll
        for (int i = 0; i < 8; i++) {          // A: 64 rows x 32 float4
            int idx = t + i * 256;
            int r = idx >> 5, p4 = idx & 31;
            ra[i] = *(const float4*)(xb + (size_t)(c0 + r) * HW + p4 * 4);
        }
#pragma unroll
        for (int i = 0; i < 4; i++) {          // B: 64 rows x 16 float4
            int idx = t + i * 256;
            int n = idx >> 4, k4 = idx & 15;
            rb[i] = *(const float4*)(W + (size_t)n * CC + c0 + k4 * 4);
        }
    };
    auto stcvt = [&]() {
#pragma unroll
        for (int i = 0; i < 8; i++) {
            int idx = t + i * 256;
            int r = idx >> 5, p4 = idx & 31;
            *(uint2*)&As[r][p4 * 4] = f4_to_h4(ra[i]);
        }
#pragma unroll
        for (int i = 0; i < 4; i++) {
            int idx = t + i * 256;
            int n = idx >> 4, k4 = idx & 15;
            *(uint2*)&Bs[n][k4 * 4] = f4_to_h4(rb[i]);
        }
    };

    ldreg(0);
    for (int ch = 0; ch < 8; ch++) {
        stcvt();
        __syncthreads();
        if (ch < 7) ldreg((ch + 1) * 64);      // LDGs overlap the MMA phase
#pragma unroll
        for (int ks = 0; ks < 4; ks++) {
            wmma::fragment<wmma::matrix_a, 16, 16, 16, __half, wmma::col_major> a[2];
            wmma::load_matrix_sync(a[0], &As[ks * 16][wm * 32], 136);
            wmma::load_matrix_sync(a[1], &As[ks * 16][wm * 32 + 16], 136);
            wmma::fragment<wmma::matrix_b, 16, 16, 16, __half, wmma::col_major> bf[2];
            wmma::load_matrix_sync(bf[0], &Bs[wn * 32][ks * 16], 72);
            wmma::load_matrix_sync(bf[1], &Bs[wn * 32 + 16][ks * 16], 72);
#pragma unroll
            for (int i = 0; i < 2; i++)
#pragma unroll
                for (int j = 0; j < 2; j++)
                    wmma::mma_sync(acc[i][j], a[i], bf[j], acc[i][j]);
        }
        __syncthreads();
    }

    // Epilogue: frags -> Osm fp32, then +bias, convert fp16, store coalesced.
#pragma unroll
    for (int i = 0; i < 2; i++)
#pragma unroll
        for (int j = 0; j < 2; j++)
            wmma::store_matrix_sync(&Osm[wm * 32 + i * 16][wn * 32 + j * 16],
                                    acc[i][j], 68, wmma::mem_row_major);
    __syncthreads();
#pragma unroll
    for (int i = 0; i < 8; i++) {              // 2048 half4 writes
        int idx = t + i * 256;
        int pix = idx >> 4, o4 = idx & 15;
        float4 f = *(float4*)&Osm[pix][o4 * 4];
        f.x += bias[o4 * 4 + 0]; f.y += bias[o4 * 4 + 1];
        f.z += bias[o4 * 4 + 2]; f.w += bias[o4 * 4 + 3];
        *(uint2*)(outp + (size_t)(mg0 + pix) * 64 + o4 * 4) = f4_to_h4(f);
    }
}

// ---------------------------------------------------------------------------
// v projection, fp16 HMMA (unchanged from R14): pvh[b,pix,n] = sum_c v*Wv
// ---------------------------------------------------------------------------
__global__ __launch_bounds__(256, 2) void proj_pv()
{
    extern __shared__ float smf[];
    __half (*As)[64][136] = (__half(*)[64][136])smf;                 // [buf][k][m]
    __half (*Bs)[128][72] = (__half(*)[128][72])((char*)smf + 2 * 64 * 136 * 2);
    float  (*Osm)[132]    = (float(*)[132])smf;                      // epilogue reuse

    const int t = threadIdx.x;
    const int warp = t >> 5;
    const int wm = warp >> 2;
    const int wn = warp & 3;
    const int nt = blockIdx.x;
    const int mg0 = blockIdx.y * 128;
    const int b = mg0 >> 12;
    const int pix0 = mg0 & 4095;

    const __half* xb = g_vh + (size_t)b * CC * HW + pix0;
    const __half* Wb = g_Wvh + (size_t)(nt * 128) * 512;

    wmma::fragment<wmma::accumulator, 16, 16, 16, float> acc[4][2];
#pragma unroll
    for (int i = 0; i < 4; i++)
#pragma unroll
        for (int j = 0; j < 2; j++) wmma::fill_fragment(acc[i][j], 0.0f);

    auto stage = [&](int buf, int c0) {
#pragma unroll
        for (int i = 0; i < 4; i++) {
            int idx = t + i * 256;
            int r = idx >> 4, s = idx & 15;
            cpa16(sptr(&As[buf][r][s * 8]), xb + (size_t)(c0 + r) * HW + s * 8);
        }
#pragma unroll
        for (int i = 0; i < 4; i++) {
            int idx = t + i * 256;
            int n = idx >> 3, s = idx & 7;
            cpa16(sptr(&Bs[buf][n][s * 8]), Wb + (size_t)n * 512 + c0 + s * 8);
        }
        CP_COMMIT();
    };

    stage(0, 0);
    for (int kc = 0; kc < 8; kc++) {
        const int cur = kc & 1;
        if (kc < 7) { stage(cur ^ 1, (kc + 1) * 64); CP_WAIT(1); }
        else        { CP_WAIT(0); }
        __syncthreads();
#pragma unroll
        for (int ks = 0; ks < 4; ks++) {
            wmma::fragment<wmma::matrix_a, 16, 16, 16, __half, wmma::col_major> a[4];
#pragma unroll
            for (int i = 0; i < 4; i++)
                wmma::load_matrix_sync(a[i], &As[cur][ks * 16][wm * 64 + i * 16], 136);
            wmma::fragment<wmma::matrix_b, 16, 16, 16, __half, wmma::col_major> bf[2];
#pragma unroll
            for (int j = 0; j < 2; j++)
                wmma::load_matrix_sync(bf[j], &Bs[cur][wn * 32 + j * 16][ks * 16], 72);
#pragma unroll
            for (int i = 0; i < 4; i++)
#pragma unroll
                for (int j = 0; j < 2; j++)
                    wmma::mma_sync(acc[i][j], a[i], bf[j], acc[i][j]);
        }
        __syncthreads();
    }

#pragma unroll
    for (int i = 0; i < 4; i++)
#pragma unroll
        for (int j = 0; j < 2; j++)
            wmma::store_matrix_sync(&Osm[wm * 64 + i * 16][wn * 32 + j * 16],
                                    acc[i][j], 132, wmma::mem_row_major);
    __syncthreads();
#pragma unroll
    for (int i = 0; i < 16; i++) {
        int idx = t + i * 256;
        int row = idx >> 5, c4 = idx & 31;
        float4 f = *(float4*)&Osm[row][c4 * 4];
        *(uint2*)(g_pvh + (size_t)(mg0 + row) * CC + nt * 128 + c4 * 4) = f4_to_h4(f);
    }
}

// ---------------------------------------------------------------------------
// Attention scores, fp16 WMMA (pq/pk fp16 with bias already included).
// blockIdx.z = mode. mode 0: per (b,w) S[h][g] + diag mask; mode 1: per (b,h).
// 8 warps x 2 tiles of 16x16; K=64 (4 HMMA per tile).
// ---------------------------------------------------------------------------
__global__ __launch_bounds__(256) void scores_h()
{
    __shared__ __half As[64][72];
    __shared__ __half Bs[64][72];
    __shared__ float  Osm[64][68];
    const int t = threadIdx.x;
    const int warp = t >> 5;
    const int q = blockIdx.x;
    const int b = blockIdx.y;
    const int mode = blockIdx.z;

    size_t base; int rs;
    if (mode == 0) { base = ((size_t)b * HW + q) * 64;      rs = 64 * 64; }
    else           { base = ((size_t)b * HW + q * 64) * 64; rs = 64;      }

#pragma unroll
    for (int i = 0; i < 2; i++) {              // 512 x 16B per matrix
        int idx = t + i * 256;
        int r = idx >> 3, s = idx & 7;
        cpa16(sptr(&As[r][s * 8]), g_pqh + base + (size_t)r * rs + s * 8);
        cpa16(sptr(&Bs[r][s * 8]), g_pkh + base + (size_t)r * rs + s * 8);
    }
    CP_COMMIT(); CP_WAIT(0);
    __syncthreads();

#pragma unroll
    for (int j = 0; j < 2; j++) {
        int tile = warp + j * 8;               // 16 tiles of 16x16
        int tr = (tile & 3) * 16, tc = (tile >> 2) * 16;
        wmma::fragment<wmma::accumulator, 16, 16, 16, float> acc;
        wmma::fill_fragment(acc, 0.0f);
#pragma unroll
        for (int ks = 0; ks < 4; ks++) {
            wmma::fragment<wmma::matrix_a, 16, 16, 16, __half, wmma::row_major> a;
            wmma::load_matrix_sync(a, &As[tr][ks * 16], 72);
            wmma::fragment<wmma::matrix_b, 16, 16, 16, __half, wmma::col_major> bf;
            wmma::load_matrix_sync(bf, &Bs[tc][ks * 16], 72);
            wmma::mma_sync(acc, a, bf, acc);
        }
        wmma::store_matrix_sync(&Osm[tr][tc], acc, 68, wmma::mem_row_major);
    }
    __syncthreads();

#pragma unroll
    for (int i = 0; i < 16; i++) {             // 4096 scalar writes
        int idx = t + i * 256;
        int r = idx >> 6, c = idx & 63;
        float v = Osm[r][c];
        size_t o;
        if (mode == 0) {
            if (r == c) v = -1e30f;
            o = (((size_t)b * HH + r) * WW + q) * 128 + c;
        } else {
            o = (((size_t)b * HH + q) * WW + r) * 128 + 64 + c;
        }
        g_att[o] = v;
    }
}

// ---------------------------------------------------------------------------
// Softmax over 128 concatenated logits; one warp per row.
// ---------------------------------------------------------------------------
__global__ __launch_bounds__(256) void softmax_kernel()
{
    const int r    = (blockIdx.x * 256 + threadIdx.x) >> 5;
    const int lane = threadIdx.x & 31;
    float4* row = (float4*)(g_att + (size_t)r * 128);
    float4 v = row[lane];
    float m = fmaxf(fmaxf(v.x, v.y), fmaxf(v.z, v.w));
#pragma unroll
    for (int o = 16; o > 0; o >>= 1) m = fmaxf(m, __shfl_xor_sync(0xffffffffu, m, o));
    v.x = __expf(v.x - m); v.y = __expf(v.y - m);
    v.z = __expf(v.z - m); v.w = __expf(v.w - m);
    float s = v.x + v.y + v.z + v.w;
#pragma unroll
    for (int o = 16; o > 0; o >>= 1) s += __shfl_xor_sync(0xffffffffu, s, o);
    float inv = 1.0f / s;
    v.x *= inv; v.y *= inv; v.z *= inv; v.w *= inv;
    row[lane] = v;
}

// ---------------------------------------------------------------------------
// tmpH[b,w,h,c] = sum_g attH[b,h,w,g] * pvh[b,pix(g,w),c]   (fp16 MMA, fp16 out)
// ---------------------------------------------------------------------------
__global__ __launch_bounds__(256, 2) void tmph_h()
{
    extern __shared__ float smf[];
    __half (*Att)[72]     = (__half(*)[72])smf;                       // [h][g]
    __half (*Ps)[64][136] = (__half(*)[64][136])((char*)smf + 64 * 72 * 2);
    float  (*OsmT)[132]   = (float(*)[132])((char*)smf + 64 * 72 * 2 + 2 * 64 * 136 * 2);
    const int t = threadIdx.x, w = blockIdx.x, b = blockIdx.y;
    const int warp = t >> 5;
    const int wh = warp >> 1;
    const int wc = warp & 1;

    auto stage = [&](int buf, int c0) {
#pragma unroll
        for (int i = 0; i < 4; i++) {
            int idx = t + i * 256;
            int g = idx >> 4, s = idx & 15;
            cpa16(sptr(&Ps[buf][g][s * 8]),
                  g_pvh + ((size_t)b * HW + g * WW + w) * CC + c0 + s * 8);
        }
        CP_COMMIT();
    };

    stage(0, 0);
#pragma unroll
    for (int i = 0; i < 4; i++) {              // Att: fp32 -> fp16
        int idx = t + i * 256;
        int h = idx >> 4, g4 = idx & 15;
        float4 f = *(const float4*)(g_att + (((size_t)b * HH + h) * WW + w) * 128 + g4 * 4);
        *(uint2*)&Att[h][g4 * 4] = f4_to_h4(f);
    }

    for (int kc = 0; kc < 4; kc++) {
        const int cur = kc & 1;
        const int c0 = kc * 128;
        if (kc < 3) { stage(cur ^ 1, c0 + 128); CP_WAIT(1); }
        else        { CP_WAIT(0); }
        __syncthreads();

        wmma::fragment<wmma::accumulator, 16, 16, 16, float> acc[4];
#pragma unroll
        for (int i = 0; i < 4; i++) wmma::fill_fragment(acc[i], 0.0f);
#pragma unroll
        for (int ks = 0; ks < 4; ks++) {
            wmma::fragment<wmma::matrix_a, 16, 16, 16, __half, wmma::row_major> a;
            wmma::load_matrix_sync(a, &Att[wh * 16][ks * 16], 72);
#pragma unroll
            for (int ci = 0; ci < 4; ci++) {
                wmma::fragment<wmma::matrix_b, 16, 16, 16, __half, wmma::row_major> bf;
                wmma::load_matrix_sync(bf, &Ps[cur][ks * 16][wc * 64 + ci * 16], 136);
                wmma::mma_sync(acc[ci], a, bf, acc[ci]);
            }
        }
#pragma unroll
        for (int ci = 0; ci < 4; ci++)
            wmma::store_matrix_sync(&OsmT[wh * 16][wc * 64 + ci * 16], acc[ci], 132,
                                    wmma::mem_row_major);
        __syncthreads();
#pragma unroll
        for (int i = 0; i < 8; i++) {          // 2048 half4 writes
            int idx = t + i * 256;
            int row = idx >> 5, c4 = idx & 31;
            float4 f = *(float4*)&OsmT[row][c4 * 4];
            *(uint2*)(g_tmpHh + (((size_t)b * WW + w) * HH + row) * CC + c0 + c4 * 4) =
                f4_to_h4(f);
        }
        __syncthreads();
    }
}

// ---------------------------------------------------------------------------
// Final per (b,h): Sw[w][c] = sum_f attW[b,h,w,f] * pvh[b,pix(h,f),c] (fp16 MMA)
// out[b,c,h,w] = value + gamma * (Sw + tmpHh[b,w,h,c] + bv[c])
// ---------------------------------------------------------------------------
__global__ __launch_bounds__(256, 2) void final_h(
    const float* __restrict__ value, const float* __restrict__ bv,
    const float* __restrict__ gamma, float* __restrict__ out)
{
    extern __shared__ float smf[];
    __half (*Att)[72]     = (__half(*)[72])smf;                        // [w][f]
    __half (*Ps)[64][136] = (__half(*)[64][136])((char*)smf + 64 * 72 * 2);
    float  (*Osm)[132]    = (float(*)[132])((char*)smf + 64 * 72 * 2 + 2 * 64 * 136 * 2);
    const int t = threadIdx.x, h = blockIdx.x, b = blockIdx.y;
    const int warp = t >> 5;
    const int ww = warp >> 1;
    const int wc = warp & 1;
    const float gm = gamma[0];

    auto stage = [&](int buf, int c0) {
#pragma unroll
        for (int i = 0; i < 4; i++) {
            int idx = t + i * 256;
            int f = idx >> 4, s = idx & 15;
            cpa16(sptr(&Ps[buf][f][s * 8]),
                  g_pvh + ((size_t)b * HW + h * WW + f) * CC + c0 + s * 8);
        }
        CP_COMMIT();
    };

    stage(0, 0);
#pragma unroll
    for (int i = 0; i < 4; i++) {
        int idx = t + i * 256;
        int w = idx >> 4, f4 = idx & 15;
        float4 f = *(const float4*)(
            g_att + (((size_t)b * HH + h) * WW + w) * 128 + 64 + f4 * 4);
        *(uint2*)&Att[w][f4 * 4] = f4_to_h4(f);
    }

    const int w4 = t & 15;          // epilogue: 4 consecutive w
    const int cB = t >> 4;          // epilogue: 8 consecutive c

    for (int kc = 0; kc < 4; kc++) {
        const int cur = kc & 1;
        const int c0 = kc * 128;
        if (kc < 3) { stage(cur ^ 1, c0 + 128); CP_WAIT(1); }
        else        { CP_WAIT(0); }
        __syncthreads();

        wmma::fragment<wmma::accumulator, 16, 16, 16, float> acc[4];
#pragma unroll
        for (int i = 0; i < 4; i++) wmma::fill_fragment(acc[i], 0.0f);
#pragma unroll
        for (int ks = 0; ks < 4; ks++) {
            wmma::fragment<wmma::matrix_a, 16, 16, 16, __half, wmma::row_major> a;
            wmma::load_matrix_sync(a, &Att[ww * 16][ks * 16], 72);
#pragma unroll
            for (int ci = 0; ci < 4; ci++) {
                wmma::fragment<wmma::matrix_b, 16, 16, 16, __half, wmma::row_major> bf;
                wmma::load_matrix_sync(bf, &Ps[cur][ks * 16][wc * 64 + ci * 16], 136);
                wmma::mma_sync(acc[ci], a, bf, acc[ci]);
            }
        }
#pragma unroll
        for (int ci = 0; ci < 4; ci++)
            wmma::store_matrix_sync(&Osm[ww * 16][wc * 64 + ci * 16], acc[ci], 132,
                                    wmma::mem_row_major);
        __syncthreads();

        float th[4][8];
#pragma unroll
        for (int wi = 0; wi < 4; wi++) {
            const __half* tp = g_tmpHh +
                (((size_t)b * WW + w4 * 4 + wi) * HH + h) * CC + c0 + cB * 8;
            uint4 u = *(const uint4*)tp;       // 8 halves
            __half2* hp = (__half2*)&u;
#pragma unroll
            for (int k = 0; k < 4; k++) {
                float2 f2 = __half22float2(hp[k]);
                th[wi][k * 2 + 0] = f2.x;
                th[wi][k * 2 + 1] = f2.y;
            }
        }
#pragma unroll
        for (int ci = 0; ci < 8; ci++) {
            int c = c0 + cB * 8 + ci;
            float bvv = bv[c];
            size_t vbase = (((size_t)b * CC + c) * HH + h) * WW;
            float4 vv = ((const float4*)(value + vbase))[w4];
            float4 ov;
            ov.x = vv.x + gm * (Osm[w4 * 4 + 0][cB * 8 + ci] + th[0][ci] + bvv);
            ov.y = vv.y + gm * (Osm[w4 * 4 + 1][cB * 8 + ci] + th[1][ci] + bvv);
            ov.z = vv.z + gm * (Osm[w4 * 4 + 2][cB * 8 + ci] + th[2][ci] + bvv);
            ov.w = vv.w + gm * (Osm[w4 * 4 + 3][cB * 8 + ci] + th[3][ci] + bvv);
            ((float4*)(out + vbase))[w4] = ov;
        }
        __syncthreads();
    }
}

// ---------------------------------------------------------------------------
#define SMEM_QK  (128 * 68 * 4)                                       // 34816 (>= mainloop 26624)
#define SMEM_PV  (2 * 64 * 136 * 2 + 2 * 128 * 72 * 2)                // 71680 (>= Osm 67584)
#define SMEM_TH  (64 * 72 * 2 + 2 * 64 * 136 * 2 + 64 * 132 * 4)      // 77824
#define SMEM_FN  (64 * 72 * 2 + 2 * 64 * 136 * 2 + 64 * 132 * 4)      // 77824

extern "C" void kernel_launch(void* const* d_in, const int* in_sizes, int n_in,
                              void* d_out, int out_size)
{
    (void)in_sizes; (void)n_in; (void)out_size;
    const float* query = (const float*)d_in[0];
    const float* key_t = (const float*)d_in[1];
    const float* value = (const float*)d_in[2];
    const float* Wq    = (const float*)d_in[3];
    const float* bq    = (const float*)d_in[4];
    const float* Wk    = (const float*)d_in[5];
    const float* bk    = (const float*)d_in[6];
    const float* Wv    = (const float*)d_in[7];
    const float* bv    = (const float*)d_in[8];
    const float* gamma = (const float*)d_in[9];
    float* out = (float*)d_out;

    cudaFuncSetAttribute(proj_qk, cudaFuncAttributeMaxDynamicSharedMemorySize, SMEM_QK);
    cudaFuncSetAttribute(proj_pv, cudaFuncAttributeMaxDynamicSharedMemorySize, SMEM_PV);
    cudaFuncSetAttribute(tmph_h,  cudaFuncAttributeMaxDynamicSharedMemorySize, SMEM_TH);
    cudaFuncSetAttribute(final_h, cudaFuncAttributeMaxDynamicSharedMemorySize, SMEM_FN);

    // Slot 4 (ncu-captured) = the new fp16 proj_qk.
    prep_v<<<16384, 256>>>(value);                                          // 1
    prep_w<<<256, 256>>>(Wv);                                               // 2
    proj_pv<<<dim3(4, 256), 256, SMEM_PV>>>();                              // 3
    proj_qk<<<dim3(256, 2), 256, SMEM_QK>>>(query, Wq, key_t, Wk, bq, bk);  // 4 <- profiled
    scores_h<<<dim3(64, BB, 2), 256>>>();                                   // 5
    softmax_kernel<<<4096, 256>>>();                                        // 6
    tmph_h<<<dim3(WW, BB), 256, SMEM_TH>>>();                               // 7
    final_h<<<dim3(HH, BB), 256, SMEM_FN>>>(value, bv, gamma, out);         // 8
}